// round 11
// baseline (speedup 1.0000x reference)
#include <cuda_runtime.h>
#include <cuda_bf16.h>
#include <cuda_fp16.h>
#include <cstdint>

#define NU 100000
#define NS 50000
#define NG 50
#define NW 20000
#define NT 10
#define CC 64
#define FF 384
#define E_US 1000000
#define E_GS 150000
#define E_WS 50000
#define E_TS 50000
#define E_LI 200000

#define CNT_U   0
#define CNT_SU  (NU)
#define CNT_SG  (NU+NS)
#define CNT_SW  (NU+2*NS)
#define CNT_ST  (NU+3*NS)
#define CNT_G   (NU+4*NS)
#define CNT_W   (NU+4*NS+NG)
#define CNT_T   (NU+4*NS+NG+NW)
#define CNT_TOT (NU+4*NS+NG+NW+NT)

#define N_SCAN  (NU + 4*NS)
#define CSR_TOT (2*E_US + E_GS + E_WS + E_TS)
#define CHUNK   1024
#define NCHUNK  ((N_SCAN + CHUNK - 1) / CHUNK)

#define AGG_G 0
#define AGG_W ((size_t)NG*CC)
#define AGG_T ((size_t)(NG+NW)*CC)
#define AGG_TOT ((size_t)(NG+NW+NT)*CC)

#define U_BLK 782
#define S_BLK 391
#define W_BLK 157

// ---- preconverted weight store (bf16 hi/lo pairs, [64][K/2] u32 per matrix) ----
#define PRE_WU  0
#define PRE_WSW 12288
#define PREK(i) (24576 + (i)*2048)
// Wl1_i -> PREK(i), Wr1_i -> PREK(8+i), Wl2_i -> PREK(16+i), Wr2_i -> PREK(24+i),
// WrS1 -> PREK(32), WrS2 -> PREK(33)
#define PRE_SZ  (24576 + 34*2048)

// ---------------- scratch ----------------
__device__ int   g_cnt[CNT_TOT + N_SCAN];
__device__ int   g_off[N_SCAN + 1];
__device__ int   g_csum[NCHUNK];
__device__ int   g_csr[CSR_TOT];
__device__ float g_agg[AGG_TOT];
__device__ uint32_t g_whi[PRE_SZ], g_wlo[PRE_SZ];

__device__ float g_xs[NS*CC];
__device__ float g_yu[NU*CC], g_ys[NS*CC];
__device__ float g_xu2[NU*CC], g_xs2[NS*CC];
__device__ __half g_tU[NU*CC], g_tS[NS*CC], g_tG[NG*CC], g_tW[NW*CC], g_tT[NT*CC];
__device__ __half g_tU2[NU*CC], g_tS2[NS*CC], g_tG2[NG*CC], g_tW2[NW*CC], g_tT2[NT*CC];
__device__ float g_xwp[NW*CC], g_xgp[NG*CC], g_xtp[NT*CC];
__device__ float g_blS1[CC], g_blS2[CC];

// ---------------- bf16 split helpers ----------------
__device__ __forceinline__ void split2(float x, float y, uint32_t& hi, uint32_t& lo) {
    __nv_bfloat162 h = __floats2bfloat162_rn(x, y);
    float2 hf = __bfloat1622float2(h);
    __nv_bfloat162 l = __floats2bfloat162_rn(x - hf.x, y - hf.y);
    hi = *(uint32_t*)&h;
    lo = *(uint32_t*)&l;
}
__device__ __forceinline__ void mma16(float* d, const uint32_t* a, uint32_t b0, uint32_t b1) {
    asm("mma.sync.aligned.m16n8k16.row.col.f32.bf16.bf16.f32 "
        "{%0,%1,%2,%3}, {%4,%5,%6,%7}, {%8,%9}, {%0,%1,%2,%3};"
        : "+f"(d[0]), "+f"(d[1]), "+f"(d[2]), "+f"(d[3])
        : "r"(a[0]), "r"(a[1]), "r"(a[2]), "r"(a[3]), "r"(b0), "r"(b1));
}

// float staging (only for launch-1 duals, before preconversion is ready)
__device__ __forceinline__ void stage_w(const float* W, int ld, int k0,
                                        uint32_t (*Whi)[36], uint32_t (*Wlo)[36], int tid) {
#pragma unroll
    for (int i = tid; i < 64 * 32; i += 256) {
        int n = i >> 5, kp = i & 31;
        float2 w = *(const float2*)(W + (size_t)n * ld + k0 + 2 * kp);
        split2(w.x, w.y, Whi[n][kp], Wlo[n][kp]);
    }
}

// preconverted staging: plain copies
__device__ __forceinline__ void stage_pre(int woff, int Kpairs, int kp0,
                                          uint32_t (*Whi)[36], uint32_t (*Wlo)[36], int tid) {
    const uint32_t* hi = g_whi + woff;
    const uint32_t* lo = g_wlo + woff;
#pragma unroll
    for (int i = tid; i < 64 * 32; i += 256) {
        int n = i >> 5, kp = i & 31;
        Whi[n][kp] = hi[n * Kpairs + kp0 + kp];
        Wlo[n][kp] = lo[n * Kpairs + kp0 + kp];
    }
}

__device__ __forceinline__ void mma_shared(float (*acc)[4], const uint32_t* ah, const uint32_t* al,
                                           const uint32_t (*Whi)[36], const uint32_t (*Wlo)[36],
                                           int ks, int g, int tg) {
#pragma unroll
    for (int j = 0; j < 8; j++) {
        uint32_t bh0 = Whi[j*8+g][ks*8+tg], bh1 = Whi[j*8+g][ks*8+tg+4];
        uint32_t bl0 = Wlo[j*8+g][ks*8+tg], bl1 = Wlo[j*8+g][ks*8+tg+4];
        mma16(acc[j], ah, bh0, bh1);
        mma16(acc[j], al, bh0, bh1);
        mma16(acc[j], ah, bl0, bl1);
    }
}

// fused: two m-tiles share one B-fragment read
__device__ __forceinline__ void mma_shared2(float (*acc0)[4], float (*acc1)[4],
                                            const uint32_t* ah0, const uint32_t* al0,
                                            const uint32_t* ah1, const uint32_t* al1,
                                            const uint32_t (*Whi)[36], const uint32_t (*Wlo)[36],
                                            int ks, int g, int tg) {
#pragma unroll
    for (int j = 0; j < 8; j++) {
        uint32_t bh0 = Whi[j*8+g][ks*8+tg], bh1 = Whi[j*8+g][ks*8+tg+4];
        uint32_t bl0 = Wlo[j*8+g][ks*8+tg], bl1 = Wlo[j*8+g][ks*8+tg+4];
        mma16(acc0[j], ah0, bh0, bh1);
        mma16(acc0[j], al0, bh0, bh1);
        mma16(acc0[j], ah0, bl0, bl1);
        mma16(acc1[j], ah1, bh0, bh1);
        mma16(acc1[j], al1, bh0, bh1);
        mma16(acc1[j], ah1, bl0, bl1);
    }
}

__device__ __forceinline__ void load_afrag(const float* A0, const float* A1, int kk, int relu,
                                           uint32_t* ah, uint32_t* al) {
    float2 a00 = *(const float2*)(A0 + kk);
    float2 a10 = *(const float2*)(A1 + kk);
    float2 a01 = *(const float2*)(A0 + kk + 8);
    float2 a11 = *(const float2*)(A1 + kk + 8);
    if (relu) {
        a00.x=fmaxf(a00.x,0.f); a00.y=fmaxf(a00.y,0.f);
        a10.x=fmaxf(a10.x,0.f); a10.y=fmaxf(a10.y,0.f);
        a01.x=fmaxf(a01.x,0.f); a01.y=fmaxf(a01.y,0.f);
        a11.x=fmaxf(a11.x,0.f); a11.y=fmaxf(a11.y,0.f);
    }
    split2(a00.x, a00.y, ah[0], al[0]);
    split2(a10.x, a10.y, ah[1], al[1]);
    split2(a01.x, a01.y, ah[2], al[2]);
    split2(a11.x, a11.y, ah[3], al[3]);
}

// register-chained GEMM using preconverted weights (L1-resident)
__device__ __forceinline__ void chain_pre(const float (*e)[4], int woff,
                                          float (*a2)[4], int g, int tg) {
    const uint32_t* whi = g_whi + woff;
    const uint32_t* wlo = g_wlo + woff;
#pragma unroll
    for (int jj = 0; jj < 4; jj++) {
        uint32_t ah[4], al[4];
        split2(e[2*jj][0],   e[2*jj][1],   ah[0], al[0]);
        split2(e[2*jj][2],   e[2*jj][3],   ah[1], al[1]);
        split2(e[2*jj+1][0], e[2*jj+1][1], ah[2], al[2]);
        split2(e[2*jj+1][2], e[2*jj+1][3], ah[3], al[3]);
#pragma unroll
        for (int j = 0; j < 8; j++) {
            int r = (j*8+g)*32 + 8*jj + tg;
            uint32_t bh0 = whi[r], bh1 = whi[r+4];
            uint32_t bl0 = wlo[r], bl1 = wlo[r+4];
            mma16(a2[j], ah, bh0, bh1);
            mma16(a2[j], al, bh0, bh1);
            mma16(a2[j], ah, bl0, bl1);
        }
    }
}

__device__ __forceinline__ void store_frag(const float (*acc)[4], const float* bias,
                                           float* out, int mr0, int M, int tg) {
#pragma unroll
    for (int j = 0; j < 8; j++) {
        int n = j*8 + 2*tg;
        float b0 = bias ? bias[n] : 0.f, b1 = bias ? bias[n+1] : 0.f;
        if (mr0 < M)
            *(float2*)(out + (size_t)mr0*CC + n) = make_float2(acc[j][0]+b0, acc[j][1]+b1);
        if (mr0+8 < M)
            *(float2*)(out + (size_t)(mr0+8)*CC + n) = make_float2(acc[j][2]+b0, acc[j][3]+b1);
    }
}

__device__ __forceinline__ void store_frag_h(const float (*acc)[4], __half* out,
                                             int mr0, int M, int tg) {
#pragma unroll
    for (int j = 0; j < 8; j++) {
        int n = j*8 + 2*tg;
        if (mr0 < M)
            *(__half2*)(out + (size_t)mr0*CC + n) = __floats2half2_rn(acc[j][0], acc[j][1]);
        if (mr0+8 < M)
            *(__half2*)(out + (size_t)(mr0+8)*CC + n) = __floats2half2_rn(acc[j][2], acc[j][3]);
    }
}

// ---------------- job structs ----------------
struct DualJob {                  // float-weight variant (launch 1 only)
    const float* A; const float* W0; __half* o0;
    const float* W1; const float* b1; float* o1; int M; int relu_in;
};
struct DualJobP {                 // preconverted-weight variant
    const float* A; int w0; __half* o0;
    int w1; const float* b1; float* o1; int M; int relu_in;
};
struct FBJobP {
    const float* A; int w1; const float* accin; const int* cnt;
    int wc; __half* out; int M;
};
struct P0Job {
    const float* A; int wpre; const float* bias; float* xout;
    int wc0; const float* bc0; float* oc0;
    int wc1; __half* oc1;
    int M;
};
struct ScatJob { const float* x; const int* src; const int* dst; float* out; };

// ---------------- GEMM bodies ----------------
__device__ __forceinline__ void dual_body_f(const DualJob& jb, int bx,
                                            uint32_t (*WhiA)[36], uint32_t (*WloA)[36],
                                            uint32_t (*WhiB)[36], uint32_t (*WloB)[36]) {
    const int m0 = bx * 128;
    const int tid = threadIdx.x, wid = tid >> 5, lane = tid & 31;
    const int g = lane >> 2, tg = lane & 3;

    stage_w(jb.W0, CC, 0, WhiA, WloA, tid);
    stage_w(jb.W1, CC, 0, WhiB, WloB, tid);
    __syncthreads();

    float acc[2][8][4];
#pragma unroll
    for (int w = 0; w < 2; w++)
#pragma unroll
        for (int j = 0; j < 8; j++) { acc[w][j][0]=acc[w][j][1]=acc[w][j][2]=acc[w][j][3]=0.f; }

    const int mtop = jb.M - 1;
    const int mr0 = m0 + wid * 16 + g;
    const float* A0 = jb.A + (size_t)min(mr0,     mtop) * CC;
    const float* A1 = jb.A + (size_t)min(mr0 + 8, mtop) * CC;

#pragma unroll
    for (int ks = 0; ks < 4; ks++) {
        uint32_t ah[4], al[4];
        load_afrag(A0, A1, ks*16 + 2*tg, jb.relu_in, ah, al);
        mma_shared(acc[0], ah, al, WhiA, WloA, ks, g, tg);
        mma_shared(acc[1], ah, al, WhiB, WloB, ks, g, tg);
    }
    store_frag_h(acc[0], jb.o0, mr0, jb.M, tg);
    store_frag(acc[1], jb.b1, jb.o1, mr0, jb.M, tg);
}

__device__ __forceinline__ void dual_body_p(const DualJobP& jb, int bx,
                                            uint32_t (*WhiA)[36], uint32_t (*WloA)[36],
                                            uint32_t (*WhiB)[36], uint32_t (*WloB)[36]) {
    const int m0 = bx * 128;
    const int tid = threadIdx.x, wid = tid >> 5, lane = tid & 31;
    const int g = lane >> 2, tg = lane & 3;

    stage_pre(jb.w0, 32, 0, WhiA, WloA, tid);
    stage_pre(jb.w1, 32, 0, WhiB, WloB, tid);
    __syncthreads();

    float acc[2][8][4];
#pragma unroll
    for (int w = 0; w < 2; w++)
#pragma unroll
        for (int j = 0; j < 8; j++) { acc[w][j][0]=acc[w][j][1]=acc[w][j][2]=acc[w][j][3]=0.f; }

    const int mtop = jb.M - 1;
    const int mr0 = m0 + wid * 16 + g;
    const float* A0 = jb.A + (size_t)min(mr0,     mtop) * CC;
    const float* A1 = jb.A + (size_t)min(mr0 + 8, mtop) * CC;

#pragma unroll
    for (int ks = 0; ks < 4; ks++) {
        uint32_t ah[4], al[4];
        load_afrag(A0, A1, ks*16 + 2*tg, jb.relu_in, ah, al);
        mma_shared(acc[0], ah, al, WhiA, WloA, ks, g, tg);
        mma_shared(acc[1], ah, al, WhiB, WloB, ks, g, tg);
    }
    store_frag_h(acc[0], jb.o0, mr0, jb.M, tg);
    store_frag(acc[1], jb.b1, jb.o1, mr0, jb.M, tg);
}

__device__ __forceinline__ void fb_body_p(const FBJobP& jb, int bx,
                                          uint32_t (*Whi)[36], uint32_t (*Wlo)[36]) {
    const int m0 = bx * 128;
    const int tid = threadIdx.x, wid = tid >> 5, lane = tid & 31;
    const int g = lane >> 2, tg = lane & 3;

    stage_pre(jb.w1, 32, 0, Whi, Wlo, tid);
    __syncthreads();

    float acc1[8][4];
#pragma unroll
    for (int j = 0; j < 8; j++) { acc1[j][0]=acc1[j][1]=acc1[j][2]=acc1[j][3]=0.f; }

    const int mtop = jb.M - 1;
    const int mr0 = m0 + wid * 16 + g;
    const int r0 = min(mr0, mtop), r1 = min(mr0 + 8, mtop);
    const float* A0 = jb.A + (size_t)r0 * CC;
    const float* A1 = jb.A + (size_t)r1 * CC;

#pragma unroll
    for (int ks = 0; ks < 4; ks++) {
        uint32_t ah[4], al[4];
        load_afrag(A0, A1, ks*16 + 2*tg, 0, ah, al);
        mma_shared(acc1, ah, al, Whi, Wlo, ks, g, tg);
    }

    const float s0 = 1.f / fmaxf((float)jb.cnt[r0], 1.f);
    const float s1 = 1.f / fmaxf((float)jb.cnt[r1], 1.f);
#pragma unroll
    for (int j = 0; j < 8; j++) {
        int n = j*8 + 2*tg;
        float2 c0 = *(const float2*)(jb.accin + (size_t)r0 * CC + n);
        float2 c1 = *(const float2*)(jb.accin + (size_t)r1 * CC + n);
        acc1[j][0] = fmaxf(acc1[j][0]*s0 + c0.x, 0.f);
        acc1[j][1] = fmaxf(acc1[j][1]*s0 + c0.y, 0.f);
        acc1[j][2] = fmaxf(acc1[j][2]*s1 + c1.x, 0.f);
        acc1[j][3] = fmaxf(acc1[j][3]*s1 + c1.y, 0.f);
    }

    float a2[8][4];
#pragma unroll
    for (int j = 0; j < 8; j++) { a2[j][0]=a2[j][1]=a2[j][2]=a2[j][3]=0.f; }
    chain_pre(acc1, jb.wc, a2, g, tg);
    store_frag_h(a2, jb.out, mr0, jb.M, tg);
}

// ---------------- launch 1: small duals + weight prep/preconvert + deg count ----
#define PD_PREP (W_BLK + 2)
#define PD_CONV (PD_PREP + 16)
#define PD_NCONV 64
#define PD_DEG  (PD_CONV + PD_NCONV)
#define PD_DEGBLK 512
#define PD_TOT  (PD_DEG + PD_DEGBLK)

__global__ void __launch_bounds__(256) prep_deg_duals(
    const DualJob jw, const DualJob jg, const DualJob jt,
    const float* __restrict__ Wu, const float* __restrict__ Wsw,
    const float* __restrict__ Wl1, const float* __restrict__ bl1,
    const float* __restrict__ Wr1,
    const float* __restrict__ Wl2, const float* __restrict__ bl2,
    const float* __restrict__ Wr2,
    const int* __restrict__ u2s, const int* __restrict__ g2s,
    const int* __restrict__ w2s, const int* __restrict__ t2s,
    int* __restrict__ cnt)
{
    __shared__ uint32_t Whi[2][64][36], Wlo[2][64][36];
    int bx = blockIdx.x;
    if (bx < W_BLK)     { dual_body_f(jw, bx, Whi[0], Wlo[0], Whi[1], Wlo[1]); return; }
    if (bx == W_BLK)    { dual_body_f(jg, 0,  Whi[0], Wlo[0], Whi[1], Wlo[1]); return; }
    if (bx == W_BLK+1)  { dual_body_f(jt, 0,  Whi[0], Wlo[0], Whi[1], Wlo[1]); return; }
    if (bx < PD_CONV) {
        int i = (bx - PD_PREP) * 256 + threadIdx.x;
        if (i < 2048) {
            float x1=0.f,y1=0.f,x2=0.f,y2=0.f;
#pragma unroll
            for (int m = 0; m < 4; m++) {
                const float* w1 = Wr1 + (size_t)(2*m)*4096;
                const float* w2 = Wr2 + (size_t)(2*m)*4096;
                x1 += w1[2*i]; y1 += w1[2*i+1];
                x2 += w2[2*i]; y2 += w2[2*i+1];
            }
            split2(x1, y1, g_whi[PREK(32)+i], g_wlo[PREK(32)+i]);
            split2(x2, y2, g_whi[PREK(33)+i], g_wlo[PREK(33)+i]);
        }
        if (i < CC) {
            g_blS1[i] = bl1[i] + bl1[2*CC+i] + bl1[4*CC+i] + bl1[6*CC+i];
            g_blS2[i] = bl2[i] + bl2[2*CC+i] + bl2[4*CC+i] + bl2[6*CC+i];
        }
        return;
    }
    if (bx < PD_DEG) {
        const float* src[6] = { Wu, Wsw, Wl1, Wr1, Wl2, Wr2 };
        const int dst[6]    = { PRE_WU, PRE_WSW, PREK(0), PREK(8), PREK(16), PREK(24) };
        const int end[6]    = { 12288, 24576, 40960, 57344, 73728, 90112 };
        const int stride = PD_NCONV * 256;
        for (int i = (bx - PD_CONV) * 256 + threadIdx.x; i < 90112; i += stride) {
            int s = 0;
            while (i >= end[s]) s++;
            int local = i - (s ? end[s-1] : 0);
            float2 w = *(const float2*)(src[s] + 2*(size_t)local);
            split2(w.x, w.y, g_whi[dst[s]+local], g_wlo[dst[s]+local]);
        }
        return;
    }
    const int stride = PD_DEGBLK * 256;
    int base = (bx - PD_DEG) * 256 + threadIdx.x;
    for (int i = base; i < E_US; i += stride) {
        atomicAdd(cnt + CNT_U  + u2s[i], 1);
        atomicAdd(cnt + CNT_SU + u2s[E_US + i], 1);
    }
    for (int i = base; i < E_GS; i += stride) {
        atomicAdd(cnt + CNT_G  + g2s[i], 1);
        atomicAdd(cnt + CNT_SG + g2s[E_GS + i], 1);
    }
    for (int i = base; i < E_WS; i += stride) {
        atomicAdd(cnt + CNT_W  + w2s[i], 1);
        atomicAdd(cnt + CNT_SW + w2s[E_WS + i], 1);
    }
    for (int i = base; i < E_TS; i += stride) {
        atomicAdd(cnt + CNT_T  + t2s[i], 1);
        atomicAdd(cnt + CNT_ST + t2s[E_TS + i], 1);
    }
}

// ---------------- scans ----------------
__global__ void scan1(const int* __restrict__ cnt, int* __restrict__ csum) {
    __shared__ int sh[8];
    int c = blockIdx.x, t = threadIdx.x, base = c * CHUNK;
    int s = 0;
#pragma unroll
    for (int q = 0; q < 4; q++) {
        int idx = base + t*4 + q;
        if (idx < N_SCAN) s += cnt[idx];
    }
    for (int o = 16; o; o >>= 1) s += __shfl_down_sync(~0u, s, o);
    if ((t & 31) == 0) sh[t >> 5] = s;
    __syncthreads();
    if (t == 0) { int tot = 0; for (int w = 0; w < 8; w++) tot += sh[w]; csum[c] = tot; }
}

__global__ void scan23(const int* __restrict__ cnt, const int* __restrict__ csum,
                       int* __restrict__ off) {
    __shared__ int sh[8], sh2[8], basev;
    int c = blockIdx.x, t = threadIdx.x;
    int lane = t & 31, w = t >> 5;

    int p = 0;
    for (int i = t; i < c; i += 256) p += csum[i];
    for (int o = 16; o; o >>= 1) p += __shfl_down_sync(~0u, p, o);
    if (lane == 0) sh2[w] = p;
    __syncthreads();
    if (t == 0) { int a = 0; for (int i = 0; i < 8; i++) a += sh2[i]; basev = a; }
    __syncthreads();
    const int cbase = basev;

    int base = c * CHUNK;
    int v[4]; int s = 0;
#pragma unroll
    for (int q = 0; q < 4; q++) {
        int idx = base + t*4 + q;
        v[q] = (idx < N_SCAN) ? cnt[idx] : 0;
        s += v[q];
    }
    int incl = s;
    for (int o = 1; o < 32; o <<= 1) {
        int x = __shfl_up_sync(~0u, incl, o);
        if (lane >= o) incl += x;
    }
    if (lane == 31) sh[w] = incl;
    __syncthreads();
    if (t == 0) { int a = 0; for (int i = 0; i < 8; i++) { int x = sh[i]; sh[i] = a; a += x; } }
    __syncthreads();
    int excl = incl - s + sh[w] + cbase;
#pragma unroll
    for (int q = 0; q < 4; q++) {
        int idx = base + t*4 + q;
        if (idx < N_SCAN) off[idx] = excl;
        excl += v[q];
        if (idx == N_SCAN - 1) off[N_SCAN] = excl;
    }
}

// ---------------- p0 mega: M=256 per block (2 m-tiles/warp), packed 1-D ----------------
#define P0_JU   391                       // cdiv(NU,256)
#define P0_JS2  196                       // cdiv(NS,256)
#define P0_FILL (P0_JU + P0_JS2)
#define P0_FILLBLK 3907
#define P0_TOT  (P0_FILL + P0_FILLBLK)

__global__ void __launch_bounds__(256) p0_mega(
    const P0Job j0, const P0Job j1,
    const int* __restrict__ u2s, const int* __restrict__ g2s,
    const int* __restrict__ w2s, const int* __restrict__ t2s,
    const int* __restrict__ off, int* __restrict__ cur, int* __restrict__ csr)
{
    __shared__ uint32_t Whi[2][64][36], Wlo[2][64][36];
    int bx = blockIdx.x;
    if (bx >= P0_FILL) {
        int i = (bx - P0_FILL) * 256 + threadIdx.x;
        if (i < E_US) {
            int u = u2s[i], s = u2s[E_US + i];
            int n0 = CNT_SU + s;
            csr[off[n0] + atomicAdd(cur + n0, 1)] = u;
            int n1 = CNT_U + u;
            csr[off[n1] + atomicAdd(cur + n1, 1)] = s;
        }
        if (i < E_GS) {
            int gg = g2s[i], s = g2s[E_GS + i];
            int n = CNT_SG + s;
            csr[off[n] + atomicAdd(cur + n, 1)] = gg;
        }
        if (i < E_WS) {
            int ww = w2s[i], s = w2s[E_WS + i];
            int n = CNT_SW + s;
            csr[off[n] + atomicAdd(cur + n, 1)] = ww;
        }
        if (i < E_TS) {
            int tt = t2s[i], s = t2s[E_TS + i];
            int n = CNT_ST + s;
            csr[off[n] + atomicAdd(cur + n, 1)] = tt;
        }
        return;
    }
    const P0Job jb = (bx >= P0_JU) ? j1 : j0;
    const int m0 = ((bx >= P0_JU) ? bx - P0_JU : bx) * 256;

    const int tid = threadIdx.x, wid = tid >> 5, lane = tid & 31;
    const int g = lane >> 2, tg = lane & 3;

    float acc[2][8][4];
#pragma unroll
    for (int mt = 0; mt < 2; mt++)
#pragma unroll
        for (int j = 0; j < 8; j++) { acc[mt][j][0]=acc[mt][j][1]=acc[mt][j][2]=acc[mt][j][3]=0.f; }

    const int mtop = jb.M - 1;
    const int mwarp = m0 + wid * 32;
    const float* A00 = jb.A + (size_t)min(mwarp + g,      mtop) * FF;
    const float* A01 = jb.A + (size_t)min(mwarp + g + 8,  mtop) * FF;
    const float* A10 = jb.A + (size_t)min(mwarp + g + 16, mtop) * FF;
    const float* A11 = jb.A + (size_t)min(mwarp + g + 24, mtop) * FF;

    stage_pre(jb.wpre, 192, 0, Whi[0], Wlo[0], tid);
    __syncthreads();

#pragma unroll
    for (int t = 0; t < 6; t++) {
        const int cb = t & 1;
        if (t < 5) stage_pre(jb.wpre, 192, (t+1)*32, Whi[cb^1], Wlo[cb^1], tid);
#pragma unroll
        for (int ks = 0; ks < 4; ks++) {
            const int kk = t*64 + ks*16 + 2*tg;
            uint32_t ah0[4], al0[4], ah1[4], al1[4];
            load_afrag(A00, A01, kk, 0, ah0, al0);
            load_afrag(A10, A11, kk, 0, ah1, al1);
            mma_shared2(acc[0], acc[1], ah0, al0, ah1, al1, Whi[cb], Wlo[cb], ks, g, tg);
        }
        __syncthreads();
    }

    // epilogue per m-tile: bias, optional xout store, sequential chains
    float a2[8][4];
#pragma unroll
    for (int mt = 0; mt < 2; mt++) {
        const int mr0 = mwarp + mt*16 + g;
#pragma unroll
        for (int j = 0; j < 8; j++) {
            int n = j*8 + 2*tg;
            float b0 = jb.bias[n], b1 = jb.bias[n+1];
            acc[mt][j][0] += b0; acc[mt][j][1] += b1;
            acc[mt][j][2] += b0; acc[mt][j][3] += b1;
        }
        if (jb.xout) store_frag(acc[mt], nullptr, jb.xout, mr0, jb.M, tg);

#pragma unroll
        for (int j = 0; j < 8; j++) { a2[j][0]=a2[j][1]=a2[j][2]=a2[j][3]=0.f; }
        chain_pre(acc[mt], jb.wc0, a2, g, tg);
        store_frag(a2, jb.bc0, jb.oc0, mr0, jb.M, tg);

#pragma unroll
        for (int j = 0; j < 8; j++) { a2[j][0]=a2[j][1]=a2[j][2]=a2[j][3]=0.f; }
        chain_pre(acc[mt], jb.wc1, a2, g, tg);
        store_frag_h(a2, jb.oc1, mr0, jb.M, tg);
    }
}

// ---------------- gather (+optional fused scatter blocks) ----------------
#define GATH_BLK 18750
#define SCAT_E   (E_GS + E_WS + E_TS)
#define SCAT_BLK ((SCAT_E * 8 + 255) / 256)

__global__ void __launch_bounds__(256) gather_scatter(
    const __half* __restrict__ tU, const __half* __restrict__ tS,
    const __half* __restrict__ tG, const __half* __restrict__ tW, const __half* __restrict__ tT,
    float* __restrict__ outS, float* __restrict__ outU,
    const int* __restrict__ off, const int* __restrict__ csr,
    const ScatJob s0, const ScatJob s1, const ScatJob s2)
{
    int bx = blockIdx.x;
    if (bx >= GATH_BLK) {
        int gid = (bx - GATH_BLK) * 256 + threadIdx.x;
        int ge = gid >> 3;
        if (ge >= SCAT_E) return;
        int part = gid & 7;
        const ScatJob jb = (ge < E_GS) ? s0 : (ge < E_GS + E_WS ? s1 : s2);
        int e = (ge < E_GS) ? ge : (ge < E_GS + E_WS ? ge - E_GS : ge - E_GS - E_WS);
        int s = jb.src[e], d = jb.dst[e];
        const float4* xp = (const float4*)(jb.x + (size_t)s * CC);
        float4*       op = (float4*)(jb.out + (size_t)d * CC);
        atomicAdd(op + part,     xp[part]);
        atomicAdd(op + part + 8, xp[part + 8]);
        return;
    }
    int gw = (bx * 256 + threadIdx.x) >> 5;
    int lane = threadIdx.x & 31;
    int hf = lane >> 4;
    int col = (lane & 15) * 4;
    float4 s = make_float4(0.f, 0.f, 0.f, 0.f);
    float* o;

    if (gw < NS) {
        const int d = gw;
        const int node[4] = { CNT_SU + d, CNT_SG + d, CNT_SW + d, CNT_ST + d };
        const __half* buf[4] = { tU, tG, tW, tT };
#pragma unroll
        for (int f = 0; f < 4; f++) {
            int b = off[node[f]], e = off[node[f] + 1];
            float4 fa = make_float4(0.f, 0.f, 0.f, 0.f);
#pragma unroll 2
            for (int i = b + hf; i < e; i += 2) {
                int src = csr[i];
                uint2 raw = *(const uint2*)(buf[f] + (size_t)src * CC + col);
                float2 v0 = __half22float2(*(__half2*)&raw.x);
                float2 v1 = __half22float2(*(__half2*)&raw.y);
                fa.x += v0.x; fa.y += v0.y; fa.z += v1.x; fa.w += v1.y;
            }
            float inv = 1.f / fmaxf((float)(e - b), 1.f);
            s.x += fa.x * inv; s.y += fa.y * inv; s.z += fa.z * inv; s.w += fa.w * inv;
        }
        o = outS + (size_t)d * CC + col;
    } else if (gw < NS + NU) {
        const int d = gw - NS;
        int b = off[CNT_U + d], e = off[CNT_U + d + 1];
        float4 fa = make_float4(0.f, 0.f, 0.f, 0.f);
#pragma unroll 2
        for (int i = b + hf; i < e; i += 2) {
            int src = csr[i];
            uint2 raw = *(const uint2*)(tS + (size_t)src * CC + col);
            float2 v0 = __half22float2(*(__half2*)&raw.x);
            float2 v1 = __half22float2(*(__half2*)&raw.y);
            fa.x += v0.x; fa.y += v0.y; fa.z += v1.x; fa.w += v1.y;
        }
        float inv = 1.f / fmaxf((float)(e - b), 1.f);
        s.x = fa.x * inv; s.y = fa.y * inv; s.z = fa.z * inv; s.w = fa.w * inv;
        o = outU + (size_t)d * CC + col;
    } else return;

    s.x += __shfl_xor_sync(~0u, s.x, 16);
    s.y += __shfl_xor_sync(~0u, s.y, 16);
    s.z += __shfl_xor_sync(~0u, s.z, 16);
    s.w += __shfl_xor_sync(~0u, s.w, 16);
    if (hf == 0) {
        float4 c = *(const float4*)o;
        *(float4*)o = make_float4(c.x + s.x, c.y + s.y, c.z + s.z, c.w + s.w);
    }
}

// ---------------- wave2: layer-2 duals + fused layer1-finalize chains ----------------
#define W2_B1 (U_BLK)
#define W2_B2 (U_BLK + S_BLK)
#define W2_B3 (U_BLK + S_BLK + W_BLK)
#define W2_TOT (U_BLK + S_BLK + W_BLK + 2)

__global__ void __launch_bounds__(256) wave2(
    const DualJobP d0, const DualJobP d1,
    const FBJobP f0, const FBJobP f1, const FBJobP f2)
{
    __shared__ uint32_t Whi[2][64][36], Wlo[2][64][36];
    int bx = blockIdx.x;
    if (bx < W2_B1)      { dual_body_p(d0, bx,          Whi[0], Wlo[0], Whi[1], Wlo[1]); return; }
    if (bx < W2_B2)      { dual_body_p(d1, bx - W2_B1,  Whi[0], Wlo[0], Whi[1], Wlo[1]); return; }
    if (bx < W2_B3)      { fb_body_p(f0, bx - W2_B2,    Whi[0], Wlo[0]); return; }
    if (bx == W2_B3)     { fb_body_p(f1, 0,             Whi[0], Wlo[0]); return; }
    fb_body_p(f2, 0, Whi[0], Wlo[0]);
}

// ---------------- classifier ----------------
__global__ void dot_score(const float* __restrict__ xu, const float* __restrict__ xs,
                          const int* __restrict__ ui, const int* __restrict__ si,
                          float* __restrict__ out, int E) {
    int gid = blockIdx.x * blockDim.x + threadIdx.x;
    int e = gid >> 4;
    int j = (gid & 15) << 2;
    int ec = (e < E) ? e : (E - 1);
    float4 a = *(const float4*)(xu + (size_t)ui[ec] * CC + j);
    float4 b = *(const float4*)(xs + (size_t)si[ec] * CC + j);
    float d = a.x*b.x + a.y*b.y + a.z*b.z + a.w*b.w;
    d += __shfl_xor_sync(0xffffffffu, d, 1);
    d += __shfl_xor_sync(0xffffffffu, d, 2);
    d += __shfl_xor_sync(0xffffffffu, d, 4);
    d += __shfl_xor_sync(0xffffffffu, d, 8);
    if ((gid & 15) == 0 && e < E) out[e] = d;
}

static inline int cdiv(int a, int b) { return (a + b - 1) / b; }

extern "C" void kernel_launch(void* const* d_in, const int* in_sizes, int n_in,
                              void* d_out, int out_size)
{
    const float* reviews  = (const float*)d_in[0];
    const float* overview = (const float*)d_in[1];
    const float* g_emb    = (const float*)d_in[2];
    const float* w_emb    = (const float*)d_in[3];
    const float* t_emb    = (const float*)d_in[4];
    const float* Wu  = (const float*)d_in[5];
    const float* bu  = (const float*)d_in[6];
    const float* Wsw = (const float*)d_in[7];
    const float* bs  = (const float*)d_in[8];
    const float* Wl1 = (const float*)d_in[9];
    const float* bl1 = (const float*)d_in[10];
    const float* Wr1 = (const float*)d_in[11];
    const float* Wl2 = (const float*)d_in[12];
    const float* bl2 = (const float*)d_in[13];
    const float* Wr2 = (const float*)d_in[14];
    const int* e_u2s = (const int*)d_in[15];
    const int* e_g2s = (const int*)d_in[16];
    const int* e_w2s = (const int*)d_in[17];
    const int* e_t2s = (const int*)d_in[18];
    const int* eli   = (const int*)d_in[19];
    float* out = (float*)d_out;

    int *cnt,*off,*csum,*csr;
    float *agg,*xs,*yu,*ys,*xu2,*xs2,*xwp,*xgp,*xtp;
    __half *tU,*tS,*tG,*tW,*tT,*tU2,*tS2,*tG2,*tW2,*tT2;
    float *blS1,*blS2;
    cudaGetSymbolAddress((void**)&cnt,  g_cnt);
    cudaGetSymbolAddress((void**)&off,  g_off);
    cudaGetSymbolAddress((void**)&csum, g_csum);
    cudaGetSymbolAddress((void**)&csr,  g_csr);
    cudaGetSymbolAddress((void**)&agg,  g_agg);
    cudaGetSymbolAddress((void**)&xs,   g_xs);
    cudaGetSymbolAddress((void**)&yu,   g_yu);
    cudaGetSymbolAddress((void**)&ys,   g_ys);
    cudaGetSymbolAddress((void**)&xu2,  g_xu2);
    cudaGetSymbolAddress((void**)&xs2,  g_xs2);
    cudaGetSymbolAddress((void**)&tU,   g_tU);
    cudaGetSymbolAddress((void**)&tS,   g_tS);
    cudaGetSymbolAddress((void**)&tG,   g_tG);
    cudaGetSymbolAddress((void**)&tW,   g_tW);
    cudaGetSymbolAddress((void**)&tT,   g_tT);
    cudaGetSymbolAddress((void**)&tU2,  g_tU2);
    cudaGetSymbolAddress((void**)&tS2,  g_tS2);
    cudaGetSymbolAddress((void**)&tG2,  g_tG2);
    cudaGetSymbolAddress((void**)&tW2,  g_tW2);
    cudaGetSymbolAddress((void**)&tT2,  g_tT2);
    cudaGetSymbolAddress((void**)&xwp,  g_xwp);
    cudaGetSymbolAddress((void**)&xgp,  g_xgp);
    cudaGetSymbolAddress((void**)&xtp,  g_xtp);
    cudaGetSymbolAddress((void**)&blS1, g_blS1);
    cudaGetSymbolAddress((void**)&blS2, g_blS2);

    int* cur = cnt + CNT_TOT;
    const int W44 = CC*CC;

    // ---- init ----
    cudaMemsetAsync(cnt, 0, (CNT_TOT + N_SCAN) * sizeof(int));
    cudaMemsetAsync(agg, 0, AGG_TOT * sizeof(float));

    // ---- launch 1: small duals (float W) + weight preconversion + degree count ----
    {
        DualJob jw = { w_emb, Wl1 + 4*W44, tW, Wr1 + 5*W44, bl1 + 5*CC, xwp, NW, 0 };
        DualJob jg = { g_emb, Wl1 + 2*W44, tG, Wr1 + 3*W44, bl1 + 3*CC, xgp, NG, 0 };
        DualJob jt = { t_emb, Wl1 + 6*W44, tT, Wr1 + 7*W44, bl1 + 7*CC, xtp, NT, 0 };
        prep_deg_duals<<<PD_TOT, 256>>>(jw, jg, jt, Wu, Wsw, Wl1, bl1, Wr1, Wl2, bl2, Wr2,
                                        e_u2s, e_g2s, e_w2s, e_t2s, cnt);
    }

    // ---- scans ----
    scan1<<<NCHUNK, 256>>>(cnt, csum);
    scan23<<<NCHUNK, 256>>>(cnt, csum, off);

    // ---- p0: big transforms (M=256/block, double-buffered preconverted W) + chains + fill_csr ----
    {
        P0Job ju = { reviews,  PRE_WU,  bu, nullptr,
                     PREK(9),  bl1 + 1*CC, yu,      // yu_pre = xu@Wr1_1 + bl1_1
                     PREK(0),  tU, NU };            // tU = xu@Wl1_0
        P0Job js = { overview, PRE_WSW, bs, xs,
                     PREK(32), blS1, ys,            // ys_pre = xs@WrS1 + blS1
                     PREK(1),  tS, NS };            // tS = xs@Wl1_1
        p0_mega<<<P0_TOT, 256>>>(ju, js, e_u2s, e_g2s, e_w2s, e_t2s, off, cur, csr);
    }

    // ---- gather 1 + s->g/w/t scatter (fused) ----
    {
        ScatJob s0 = { xs, e_g2s + E_GS, e_g2s, agg + AGG_G };
        ScatJob s1 = { xs, e_w2s + E_WS, e_w2s, agg + AGG_W };
        ScatJob s2 = { xs, e_t2s + E_TS, e_t2s, agg + AGG_T };
        gather_scatter<<<GATH_BLK + SCAT_BLK, 256>>>(tU, tS, tG, tW, tT, ys, yu,
                                                     off, csr, s0, s1, s2);
    }

    // ---- wave2 ----
    {
        DualJobP d0 = { yu, PREK(16), tU2, PREK(25), bl2 + 1*CC, xu2, NU, 1 };
        DualJobP d1 = { ys, PREK(17), tS2, PREK(33), blS2,       xs2, NS, 1 };
        FBJobP f0 = { agg + AGG_W, PREK(5), xwp, cnt + CNT_W, PREK(20), tW2, NW };
        FBJobP f1 = { agg + AGG_G, PREK(3), xgp, cnt + CNT_G, PREK(18), tG2, NG };
        FBJobP f2 = { agg + AGG_T, PREK(7), xtp, cnt + CNT_T, PREK(22), tT2, NT };
        wave2<<<W2_TOT, 256>>>(d0, d1, f0, f1, f2);
    }

    // ---- gather 2 ----
    {
        ScatJob sd = { nullptr, nullptr, nullptr, nullptr };
        gather_scatter<<<GATH_BLK, 256>>>(tU2, tS2, tG2, tW2, tT2, xs2, xu2,
                                          off, csr, sd, sd, sd);
    }

    // ---- classifier ----
    dot_score<<<E_LI*16/256, 256>>>(xu2, xs2, eli, eli + E_LI, out, E_LI);
}

// round 12
// speedup vs baseline: 1.0407x; 1.0407x over previous
#include <cuda_runtime.h>
#include <cuda_bf16.h>
#include <cuda_fp16.h>
#include <cstdint>

#define NU 100000
#define NS 50000
#define NG 50
#define NW 20000
#define NT 10
#define CC 64
#define FF 384
#define E_US 1000000
#define E_GS 150000
#define E_WS 50000
#define E_TS 50000
#define E_LI 200000

#define CNT_U   0
#define CNT_SU  (NU)
#define CNT_SG  (NU+NS)
#define CNT_SW  (NU+2*NS)
#define CNT_ST  (NU+3*NS)
#define CNT_G   (NU+4*NS)
#define CNT_W   (NU+4*NS+NG)
#define CNT_T   (NU+4*NS+NG+NW)
#define CNT_TOT (NU+4*NS+NG+NW+NT)

#define N_SCAN  (NU + 4*NS)
#define CSR_TOT (2*E_US + E_GS + E_WS + E_TS)
#define CHUNK   1024
#define NCHUNK  ((N_SCAN + CHUNK - 1) / CHUNK)

#define AGG_G 0
#define AGG_W ((size_t)NG*CC)
#define AGG_T ((size_t)(NG+NW)*CC)
#define AGG_TOT ((size_t)(NG+NW+NT)*CC)

#define U_BLK 782
#define S_BLK 391
#define W_BLK 157

// ---- preconverted weight store (bf16 hi/lo pairs, [64][K/2] u32 per matrix) ----
#define PRE_WU  0
#define PRE_WSW 12288
#define PREK(i) (24576 + (i)*2048)
// Wl1_i -> PREK(i), Wr1_i -> PREK(8+i), Wl2_i -> PREK(16+i), Wr2_i -> PREK(24+i),
// WrS1 -> PREK(32), WrS2 -> PREK(33)
#define PRE_SZ  (24576 + 34*2048)

// ---------------- scratch ----------------
__device__ int   g_cnt[CNT_TOT + N_SCAN];
__device__ int   g_off[N_SCAN + 1];
__device__ int   g_csum[NCHUNK];
__device__ int   g_csr[CSR_TOT];
__device__ float g_agg[AGG_TOT];
__device__ uint32_t g_whi[PRE_SZ], g_wlo[PRE_SZ];

__device__ float g_xs[NS*CC];
__device__ float g_yu[NU*CC], g_ys[NS*CC];
__device__ float g_xu2[NU*CC], g_xs2[NS*CC];
__device__ __half g_tU[NU*CC], g_tS[NS*CC], g_tG[NG*CC], g_tW[NW*CC], g_tT[NT*CC];
__device__ __half g_tU2[NU*CC], g_tS2[NS*CC], g_tG2[NG*CC], g_tW2[NW*CC], g_tT2[NT*CC];
__device__ float g_xwp[NW*CC], g_xgp[NG*CC], g_xtp[NT*CC];
__device__ float g_blS1[CC], g_blS2[CC];

// ---------------- bf16 split helpers ----------------
__device__ __forceinline__ void split2(float x, float y, uint32_t& hi, uint32_t& lo) {
    __nv_bfloat162 h = __floats2bfloat162_rn(x, y);
    float2 hf = __bfloat1622float2(h);
    __nv_bfloat162 l = __floats2bfloat162_rn(x - hf.x, y - hf.y);
    hi = *(uint32_t*)&h;
    lo = *(uint32_t*)&l;
}
__device__ __forceinline__ void mma16(float* d, const uint32_t* a, uint32_t b0, uint32_t b1) {
    asm("mma.sync.aligned.m16n8k16.row.col.f32.bf16.bf16.f32 "
        "{%0,%1,%2,%3}, {%4,%5,%6,%7}, {%8,%9}, {%0,%1,%2,%3};"
        : "+f"(d[0]), "+f"(d[1]), "+f"(d[2]), "+f"(d[3])
        : "r"(a[0]), "r"(a[1]), "r"(a[2]), "r"(a[3]), "r"(b0), "r"(b1));
}

// float staging (only for launch-1 duals, before preconversion is ready)
__device__ __forceinline__ void stage_w(const float* W, int ld, int k0,
                                        uint32_t (*Whi)[36], uint32_t (*Wlo)[36], int tid) {
#pragma unroll
    for (int i = tid; i < 64 * 32; i += 256) {
        int n = i >> 5, kp = i & 31;
        float2 w = *(const float2*)(W + (size_t)n * ld + k0 + 2 * kp);
        split2(w.x, w.y, Whi[n][kp], Wlo[n][kp]);
    }
}

// preconverted staging: plain copies
__device__ __forceinline__ void stage_pre(int woff, int Kpairs, int kp0,
                                          uint32_t (*Whi)[36], uint32_t (*Wlo)[36], int tid) {
    const uint32_t* hi = g_whi + woff;
    const uint32_t* lo = g_wlo + woff;
#pragma unroll
    for (int i = tid; i < 64 * 32; i += 256) {
        int n = i >> 5, kp = i & 31;
        Whi[n][kp] = hi[n * Kpairs + kp0 + kp];
        Wlo[n][kp] = lo[n * Kpairs + kp0 + kp];
    }
}

__device__ __forceinline__ void mma_shared(float (*acc)[4], const uint32_t* ah, const uint32_t* al,
                                           const uint32_t (*Whi)[36], const uint32_t (*Wlo)[36],
                                           int ks, int g, int tg) {
#pragma unroll
    for (int j = 0; j < 8; j++) {
        uint32_t bh0 = Whi[j*8+g][ks*8+tg], bh1 = Whi[j*8+g][ks*8+tg+4];
        uint32_t bl0 = Wlo[j*8+g][ks*8+tg], bl1 = Wlo[j*8+g][ks*8+tg+4];
        mma16(acc[j], ah, bh0, bh1);
        mma16(acc[j], al, bh0, bh1);
        mma16(acc[j], ah, bl0, bl1);
    }
}

__device__ __forceinline__ void load_afrag(const float* A0, const float* A1, int kk, int relu,
                                           uint32_t* ah, uint32_t* al) {
    float2 a00 = *(const float2*)(A0 + kk);
    float2 a10 = *(const float2*)(A1 + kk);
    float2 a01 = *(const float2*)(A0 + kk + 8);
    float2 a11 = *(const float2*)(A1 + kk + 8);
    if (relu) {
        a00.x=fmaxf(a00.x,0.f); a00.y=fmaxf(a00.y,0.f);
        a10.x=fmaxf(a10.x,0.f); a10.y=fmaxf(a10.y,0.f);
        a01.x=fmaxf(a01.x,0.f); a01.y=fmaxf(a01.y,0.f);
        a11.x=fmaxf(a11.x,0.f); a11.y=fmaxf(a11.y,0.f);
    }
    split2(a00.x, a00.y, ah[0], al[0]);
    split2(a10.x, a10.y, ah[1], al[1]);
    split2(a01.x, a01.y, ah[2], al[2]);
    split2(a11.x, a11.y, ah[3], al[3]);
}

// register-chained GEMM using preconverted weights (L1-resident)
__device__ __forceinline__ void chain_pre(const float (*e)[4], int woff,
                                          float (*a2)[4], int g, int tg) {
    const uint32_t* whi = g_whi + woff;
    const uint32_t* wlo = g_wlo + woff;
#pragma unroll
    for (int jj = 0; jj < 4; jj++) {
        uint32_t ah[4], al[4];
        split2(e[2*jj][0],   e[2*jj][1],   ah[0], al[0]);
        split2(e[2*jj][2],   e[2*jj][3],   ah[1], al[1]);
        split2(e[2*jj+1][0], e[2*jj+1][1], ah[2], al[2]);
        split2(e[2*jj+1][2], e[2*jj+1][3], ah[3], al[3]);
#pragma unroll
        for (int j = 0; j < 8; j++) {
            int r = (j*8+g)*32 + 8*jj + tg;
            uint32_t bh0 = whi[r], bh1 = whi[r+4];
            uint32_t bl0 = wlo[r], bl1 = wlo[r+4];
            mma16(a2[j], ah, bh0, bh1);
            mma16(a2[j], al, bh0, bh1);
            mma16(a2[j], ah, bl0, bl1);
        }
    }
}

__device__ __forceinline__ void store_frag(const float (*acc)[4], const float* bias,
                                           float* out, int mr0, int M, int tg) {
#pragma unroll
    for (int j = 0; j < 8; j++) {
        int n = j*8 + 2*tg;
        float b0 = bias ? bias[n] : 0.f, b1 = bias ? bias[n+1] : 0.f;
        if (mr0 < M)
            *(float2*)(out + (size_t)mr0*CC + n) = make_float2(acc[j][0]+b0, acc[j][1]+b1);
        if (mr0+8 < M)
            *(float2*)(out + (size_t)(mr0+8)*CC + n) = make_float2(acc[j][2]+b0, acc[j][3]+b1);
    }
}

__device__ __forceinline__ void store_frag_h(const float (*acc)[4], __half* out,
                                             int mr0, int M, int tg) {
#pragma unroll
    for (int j = 0; j < 8; j++) {
        int n = j*8 + 2*tg;
        if (mr0 < M)
            *(__half2*)(out + (size_t)mr0*CC + n) = __floats2half2_rn(acc[j][0], acc[j][1]);
        if (mr0+8 < M)
            *(__half2*)(out + (size_t)(mr0+8)*CC + n) = __floats2half2_rn(acc[j][2], acc[j][3]);
    }
}

// ---------------- job structs ----------------
struct DualJob {                  // float-weight variant (launch 1 only)
    const float* A; const float* W0; __half* o0;
    const float* W1; const float* b1; float* o1; int M; int relu_in;
};
struct DualJobP {                 // preconverted-weight variant
    const float* A; int w0; __half* o0;
    int w1; const float* b1; float* o1; int M; int relu_in;
};
struct FBJobP {
    const float* A; int w1; const float* accin; const int* cnt;
    int wc; __half* out; int M;
};
struct P0Job {
    const float* A; int wpre; const float* bias; float* xout;
    int wc0; const float* bc0; float* oc0;
    int wc1; __half* oc1;
    int M;
};
struct ScatJob { const float* x; const int* src; const int* dst; float* out; };

// ---------------- GEMM bodies ----------------
__device__ __forceinline__ void dual_body_f(const DualJob& jb, int bx,
                                            uint32_t (*WhiA)[36], uint32_t (*WloA)[36],
                                            uint32_t (*WhiB)[36], uint32_t (*WloB)[36]) {
    const int m0 = bx * 128;
    const int tid = threadIdx.x, wid = tid >> 5, lane = tid & 31;
    const int g = lane >> 2, tg = lane & 3;

    stage_w(jb.W0, CC, 0, WhiA, WloA, tid);
    stage_w(jb.W1, CC, 0, WhiB, WloB, tid);
    __syncthreads();

    float acc[2][8][4];
#pragma unroll
    for (int w = 0; w < 2; w++)
#pragma unroll
        for (int j = 0; j < 8; j++) { acc[w][j][0]=acc[w][j][1]=acc[w][j][2]=acc[w][j][3]=0.f; }

    const int mtop = jb.M - 1;
    const int mr0 = m0 + wid * 16 + g;
    const float* A0 = jb.A + (size_t)min(mr0,     mtop) * CC;
    const float* A1 = jb.A + (size_t)min(mr0 + 8, mtop) * CC;

#pragma unroll
    for (int ks = 0; ks < 4; ks++) {
        uint32_t ah[4], al[4];
        load_afrag(A0, A1, ks*16 + 2*tg, jb.relu_in, ah, al);
        mma_shared(acc[0], ah, al, WhiA, WloA, ks, g, tg);
        mma_shared(acc[1], ah, al, WhiB, WloB, ks, g, tg);
    }
    store_frag_h(acc[0], jb.o0, mr0, jb.M, tg);
    store_frag(acc[1], jb.b1, jb.o1, mr0, jb.M, tg);
}

__device__ __forceinline__ void dual_body_p(const DualJobP& jb, int bx,
                                            uint32_t (*WhiA)[36], uint32_t (*WloA)[36],
                                            uint32_t (*WhiB)[36], uint32_t (*WloB)[36]) {
    const int m0 = bx * 128;
    const int tid = threadIdx.x, wid = tid >> 5, lane = tid & 31;
    const int g = lane >> 2, tg = lane & 3;

    stage_pre(jb.w0, 32, 0, WhiA, WloA, tid);
    stage_pre(jb.w1, 32, 0, WhiB, WloB, tid);
    __syncthreads();

    float acc[2][8][4];
#pragma unroll
    for (int w = 0; w < 2; w++)
#pragma unroll
        for (int j = 0; j < 8; j++) { acc[w][j][0]=acc[w][j][1]=acc[w][j][2]=acc[w][j][3]=0.f; }

    const int mtop = jb.M - 1;
    const int mr0 = m0 + wid * 16 + g;
    const float* A0 = jb.A + (size_t)min(mr0,     mtop) * CC;
    const float* A1 = jb.A + (size_t)min(mr0 + 8, mtop) * CC;

#pragma unroll
    for (int ks = 0; ks < 4; ks++) {
        uint32_t ah[4], al[4];
        load_afrag(A0, A1, ks*16 + 2*tg, jb.relu_in, ah, al);
        mma_shared(acc[0], ah, al, WhiA, WloA, ks, g, tg);
        mma_shared(acc[1], ah, al, WhiB, WloB, ks, g, tg);
    }
    store_frag_h(acc[0], jb.o0, mr0, jb.M, tg);
    store_frag(acc[1], jb.b1, jb.o1, mr0, jb.M, tg);
}

__device__ __forceinline__ void fb_body_p(const FBJobP& jb, int bx,
                                          uint32_t (*Whi)[36], uint32_t (*Wlo)[36]) {
    const int m0 = bx * 128;
    const int tid = threadIdx.x, wid = tid >> 5, lane = tid & 31;
    const int g = lane >> 2, tg = lane & 3;

    stage_pre(jb.w1, 32, 0, Whi, Wlo, tid);
    __syncthreads();

    float acc1[8][4];
#pragma unroll
    for (int j = 0; j < 8; j++) { acc1[j][0]=acc1[j][1]=acc1[j][2]=acc1[j][3]=0.f; }

    const int mtop = jb.M - 1;
    const int mr0 = m0 + wid * 16 + g;
    const int r0 = min(mr0, mtop), r1 = min(mr0 + 8, mtop);
    const float* A0 = jb.A + (size_t)r0 * CC;
    const float* A1 = jb.A + (size_t)r1 * CC;

#pragma unroll
    for (int ks = 0; ks < 4; ks++) {
        uint32_t ah[4], al[4];
        load_afrag(A0, A1, ks*16 + 2*tg, 0, ah, al);
        mma_shared(acc1, ah, al, Whi, Wlo, ks, g, tg);
    }

    const float s0 = 1.f / fmaxf((float)jb.cnt[r0], 1.f);
    const float s1 = 1.f / fmaxf((float)jb.cnt[r1], 1.f);
#pragma unroll
    for (int j = 0; j < 8; j++) {
        int n = j*8 + 2*tg;
        float2 c0 = *(const float2*)(jb.accin + (size_t)r0 * CC + n);
        float2 c1 = *(const float2*)(jb.accin + (size_t)r1 * CC + n);
        acc1[j][0] = fmaxf(acc1[j][0]*s0 + c0.x, 0.f);
        acc1[j][1] = fmaxf(acc1[j][1]*s0 + c0.y, 0.f);
        acc1[j][2] = fmaxf(acc1[j][2]*s1 + c1.x, 0.f);
        acc1[j][3] = fmaxf(acc1[j][3]*s1 + c1.y, 0.f);
    }

    float a2[8][4];
#pragma unroll
    for (int j = 0; j < 8; j++) { a2[j][0]=a2[j][1]=a2[j][2]=a2[j][3]=0.f; }
    chain_pre(acc1, jb.wc, a2, g, tg);
    store_frag_h(a2, jb.out, mr0, jb.M, tg);
}

// ---------------- launch 1: small duals + weight prep/preconvert + deg count ----
#define PD_PREP (W_BLK + 2)
#define PD_CONV (PD_PREP + 16)
#define PD_NCONV 64
#define PD_DEG  (PD_CONV + PD_NCONV)
#define PD_DEGBLK 512
#define PD_TOT  (PD_DEG + PD_DEGBLK)

__global__ void __launch_bounds__(256) prep_deg_duals(
    const DualJob jw, const DualJob jg, const DualJob jt,
    const float* __restrict__ Wu, const float* __restrict__ Wsw,
    const float* __restrict__ Wl1, const float* __restrict__ bl1,
    const float* __restrict__ Wr1,
    const float* __restrict__ Wl2, const float* __restrict__ bl2,
    const float* __restrict__ Wr2,
    const int* __restrict__ u2s, const int* __restrict__ g2s,
    const int* __restrict__ w2s, const int* __restrict__ t2s,
    int* __restrict__ cnt)
{
    __shared__ uint32_t Whi[2][64][36], Wlo[2][64][36];
    int bx = blockIdx.x;
    if (bx < W_BLK)     { dual_body_f(jw, bx, Whi[0], Wlo[0], Whi[1], Wlo[1]); return; }
    if (bx == W_BLK)    { dual_body_f(jg, 0,  Whi[0], Wlo[0], Whi[1], Wlo[1]); return; }
    if (bx == W_BLK+1)  { dual_body_f(jt, 0,  Whi[0], Wlo[0], Whi[1], Wlo[1]); return; }
    if (bx < PD_CONV) {
        int i = (bx - PD_PREP) * 256 + threadIdx.x;
        if (i < 2048) {
            float x1=0.f,y1=0.f,x2=0.f,y2=0.f;
#pragma unroll
            for (int m = 0; m < 4; m++) {
                const float* w1 = Wr1 + (size_t)(2*m)*4096;
                const float* w2 = Wr2 + (size_t)(2*m)*4096;
                x1 += w1[2*i]; y1 += w1[2*i+1];
                x2 += w2[2*i]; y2 += w2[2*i+1];
            }
            split2(x1, y1, g_whi[PREK(32)+i], g_wlo[PREK(32)+i]);
            split2(x2, y2, g_whi[PREK(33)+i], g_wlo[PREK(33)+i]);
        }
        if (i < CC) {
            g_blS1[i] = bl1[i] + bl1[2*CC+i] + bl1[4*CC+i] + bl1[6*CC+i];
            g_blS2[i] = bl2[i] + bl2[2*CC+i] + bl2[4*CC+i] + bl2[6*CC+i];
        }
        return;
    }
    if (bx < PD_DEG) {
        const float* src[6] = { Wu, Wsw, Wl1, Wr1, Wl2, Wr2 };
        const int dst[6]    = { PRE_WU, PRE_WSW, PREK(0), PREK(8), PREK(16), PREK(24) };
        const int end[6]    = { 12288, 24576, 40960, 57344, 73728, 90112 };
        const int stride = PD_NCONV * 256;
        for (int i = (bx - PD_CONV) * 256 + threadIdx.x; i < 90112; i += stride) {
            int s = 0;
            while (i >= end[s]) s++;
            int local = i - (s ? end[s-1] : 0);
            float2 w = *(const float2*)(src[s] + 2*(size_t)local);
            split2(w.x, w.y, g_whi[dst[s]+local], g_wlo[dst[s]+local]);
        }
        return;
    }
    const int stride = PD_DEGBLK * 256;
    int base = (bx - PD_DEG) * 256 + threadIdx.x;
    for (int i = base; i < E_US; i += stride) {
        atomicAdd(cnt + CNT_U  + u2s[i], 1);
        atomicAdd(cnt + CNT_SU + u2s[E_US + i], 1);
    }
    for (int i = base; i < E_GS; i += stride) {
        atomicAdd(cnt + CNT_G  + g2s[i], 1);
        atomicAdd(cnt + CNT_SG + g2s[E_GS + i], 1);
    }
    for (int i = base; i < E_WS; i += stride) {
        atomicAdd(cnt + CNT_W  + w2s[i], 1);
        atomicAdd(cnt + CNT_SW + w2s[E_WS + i], 1);
    }
    for (int i = base; i < E_TS; i += stride) {
        atomicAdd(cnt + CNT_T  + t2s[i], 1);
        atomicAdd(cnt + CNT_ST + t2s[E_TS + i], 1);
    }
}

// ---------------- scans ----------------
__global__ void scan1(const int* __restrict__ cnt, int* __restrict__ csum) {
    __shared__ int sh[8];
    int c = blockIdx.x, t = threadIdx.x, base = c * CHUNK;
    int s = 0;
#pragma unroll
    for (int q = 0; q < 4; q++) {
        int idx = base + t*4 + q;
        if (idx < N_SCAN) s += cnt[idx];
    }
    for (int o = 16; o; o >>= 1) s += __shfl_down_sync(~0u, s, o);
    if ((t & 31) == 0) sh[t >> 5] = s;
    __syncthreads();
    if (t == 0) { int tot = 0; for (int w = 0; w < 8; w++) tot += sh[w]; csum[c] = tot; }
}

__global__ void scan23(const int* __restrict__ cnt, const int* __restrict__ csum,
                       int* __restrict__ off) {
    __shared__ int sh[8], sh2[8], basev;
    int c = blockIdx.x, t = threadIdx.x;
    int lane = t & 31, w = t >> 5;

    int p = 0;
    for (int i = t; i < c; i += 256) p += csum[i];
    for (int o = 16; o; o >>= 1) p += __shfl_down_sync(~0u, p, o);
    if (lane == 0) sh2[w] = p;
    __syncthreads();
    if (t == 0) { int a = 0; for (int i = 0; i < 8; i++) a += sh2[i]; basev = a; }
    __syncthreads();
    const int cbase = basev;

    int base = c * CHUNK;
    int v[4]; int s = 0;
#pragma unroll
    for (int q = 0; q < 4; q++) {
        int idx = base + t*4 + q;
        v[q] = (idx < N_SCAN) ? cnt[idx] : 0;
        s += v[q];
    }
    int incl = s;
    for (int o = 1; o < 32; o <<= 1) {
        int x = __shfl_up_sync(~0u, incl, o);
        if (lane >= o) incl += x;
    }
    if (lane == 31) sh[w] = incl;
    __syncthreads();
    if (t == 0) { int a = 0; for (int i = 0; i < 8; i++) { int x = sh[i]; sh[i] = a; a += x; } }
    __syncthreads();
    int excl = incl - s + sh[w] + cbase;
#pragma unroll
    for (int q = 0; q < 4; q++) {
        int idx = base + t*4 + q;
        if (idx < N_SCAN) off[idx] = excl;
        excl += v[q];
        if (idx == N_SCAN - 1) off[N_SCAN] = excl;
    }
}

// ---------------- p0 mega: M=128/block, occ-3 forced, packed 1-D ----------------
#define P0_JU   U_BLK                     // 782
#define P0_FILL (U_BLK + S_BLK)           // 1173
#define P0_FILLBLK 3907
#define P0_TOT  (P0_FILL + P0_FILLBLK)

__global__ void __launch_bounds__(256, 3) p0_mega(
    const P0Job j0, const P0Job j1,
    const int* __restrict__ u2s, const int* __restrict__ g2s,
    const int* __restrict__ w2s, const int* __restrict__ t2s,
    const int* __restrict__ off, int* __restrict__ cur, int* __restrict__ csr)
{
    __shared__ uint32_t Whi[2][64][36], Wlo[2][64][36];
    int bx = blockIdx.x;
    if (bx >= P0_FILL) {
        int i = (bx - P0_FILL) * 256 + threadIdx.x;
        if (i < E_US) {
            int u = u2s[i], s = u2s[E_US + i];
            int n0 = CNT_SU + s;
            csr[off[n0] + atomicAdd(cur + n0, 1)] = u;
            int n1 = CNT_U + u;
            csr[off[n1] + atomicAdd(cur + n1, 1)] = s;
        }
        if (i < E_GS) {
            int gg = g2s[i], s = g2s[E_GS + i];
            int n = CNT_SG + s;
            csr[off[n] + atomicAdd(cur + n, 1)] = gg;
        }
        if (i < E_WS) {
            int ww = w2s[i], s = w2s[E_WS + i];
            int n = CNT_SW + s;
            csr[off[n] + atomicAdd(cur + n, 1)] = ww;
        }
        if (i < E_TS) {
            int tt = t2s[i], s = t2s[E_TS + i];
            int n = CNT_ST + s;
            csr[off[n] + atomicAdd(cur + n, 1)] = tt;
        }
        return;
    }
    const P0Job jb = (bx >= P0_JU) ? j1 : j0;
    const int m0 = ((bx >= P0_JU) ? bx - P0_JU : bx) * 128;

    const int tid = threadIdx.x, wid = tid >> 5, lane = tid & 31;
    const int g = lane >> 2, tg = lane & 3;

    float acc1[8][4];
#pragma unroll
    for (int j = 0; j < 8; j++) { acc1[j][0]=acc1[j][1]=acc1[j][2]=acc1[j][3]=0.f; }

    const int mtop = jb.M - 1;
    const int mr0 = m0 + wid * 16 + g;
    const float* A0 = jb.A + (size_t)min(mr0,     mtop) * FF;
    const float* A1 = jb.A + (size_t)min(mr0 + 8, mtop) * FF;

    stage_pre(jb.wpre, 192, 0, Whi[0], Wlo[0], tid);
    __syncthreads();

#pragma unroll
    for (int t = 0; t < 6; t++) {
        const int cb = t & 1;
        if (t < 5) stage_pre(jb.wpre, 192, (t+1)*32, Whi[cb^1], Wlo[cb^1], tid);
#pragma unroll
        for (int ks = 0; ks < 4; ks++) {
            uint32_t ah[4], al[4];
            load_afrag(A0, A1, t*64 + ks*16 + 2*tg, 0, ah, al);
            mma_shared(acc1, ah, al, Whi[cb], Wlo[cb], ks, g, tg);
        }
        __syncthreads();
    }

    // bias -> acc1 is the transformed feature x
#pragma unroll
    for (int j = 0; j < 8; j++) {
        int n = j*8 + 2*tg;
        float b0 = jb.bias[n], b1 = jb.bias[n+1];
        acc1[j][0] += b0; acc1[j][1] += b1;
        acc1[j][2] += b0; acc1[j][3] += b1;
    }
    if (jb.xout) store_frag(acc1, nullptr, jb.xout, mr0, jb.M, tg);

    // sequential chains (reuse a2 registers)
    float a2[8][4];
#pragma unroll
    for (int j = 0; j < 8; j++) { a2[j][0]=a2[j][1]=a2[j][2]=a2[j][3]=0.f; }
    chain_pre(acc1, jb.wc0, a2, g, tg);
    store_frag(a2, jb.bc0, jb.oc0, mr0, jb.M, tg);

#pragma unroll
    for (int j = 0; j < 8; j++) { a2[j][0]=a2[j][1]=a2[j][2]=a2[j][3]=0.f; }
    chain_pre(acc1, jb.wc1, a2, g, tg);
    store_frag_h(a2, jb.oc1, mr0, jb.M, tg);
}

// ---------------- gather (+optional fused scatter blocks) ----------------
#define GATH_BLK 18750
#define SCAT_E   (E_GS + E_WS + E_TS)
#define SCAT_BLK ((SCAT_E * 8 + 255) / 256)

__global__ void __launch_bounds__(256) gather_scatter(
    const __half* __restrict__ tU, const __half* __restrict__ tS,
    const __half* __restrict__ tG, const __half* __restrict__ tW, const __half* __restrict__ tT,
    float* __restrict__ outS, float* __restrict__ outU,
    const int* __restrict__ off, const int* __restrict__ csr,
    const ScatJob s0, const ScatJob s1, const ScatJob s2)
{
    int bx = blockIdx.x;
    if (bx >= GATH_BLK) {
        int gid = (bx - GATH_BLK) * 256 + threadIdx.x;
        int ge = gid >> 3;
        if (ge >= SCAT_E) return;
        int part = gid & 7;
        const ScatJob jb = (ge < E_GS) ? s0 : (ge < E_GS + E_WS ? s1 : s2);
        int e = (ge < E_GS) ? ge : (ge < E_GS + E_WS ? ge - E_GS : ge - E_GS - E_WS);
        int s = jb.src[e], d = jb.dst[e];
        const float4* xp = (const float4*)(jb.x + (size_t)s * CC);
        float4*       op = (float4*)(jb.out + (size_t)d * CC);
        atomicAdd(op + part,     xp[part]);
        atomicAdd(op + part + 8, xp[part + 8]);
        return;
    }
    int gw = (bx * 256 + threadIdx.x) >> 5;
    int lane = threadIdx.x & 31;
    int hf = lane >> 4;
    int col = (lane & 15) * 4;
    float4 s = make_float4(0.f, 0.f, 0.f, 0.f);
    float* o;

    if (gw < NS) {
        const int d = gw;
        const int node[4] = { CNT_SU + d, CNT_SG + d, CNT_SW + d, CNT_ST + d };
        const __half* buf[4] = { tU, tG, tW, tT };
#pragma unroll
        for (int f = 0; f < 4; f++) {
            int b = off[node[f]], e = off[node[f] + 1];
            float4 fa = make_float4(0.f, 0.f, 0.f, 0.f);
#pragma unroll 2
            for (int i = b + hf; i < e; i += 2) {
                int src = csr[i];
                uint2 raw = *(const uint2*)(buf[f] + (size_t)src * CC + col);
                float2 v0 = __half22float2(*(__half2*)&raw.x);
                float2 v1 = __half22float2(*(__half2*)&raw.y);
                fa.x += v0.x; fa.y += v0.y; fa.z += v1.x; fa.w += v1.y;
            }
            float inv = 1.f / fmaxf((float)(e - b), 1.f);
            s.x += fa.x * inv; s.y += fa.y * inv; s.z += fa.z * inv; s.w += fa.w * inv;
        }
        o = outS + (size_t)d * CC + col;
    } else if (gw < NS + NU) {
        const int d = gw - NS;
        int b = off[CNT_U + d], e = off[CNT_U + d + 1];
        float4 fa = make_float4(0.f, 0.f, 0.f, 0.f);
#pragma unroll 2
        for (int i = b + hf; i < e; i += 2) {
            int src = csr[i];
            uint2 raw = *(const uint2*)(tS + (size_t)src * CC + col);
            float2 v0 = __half22float2(*(__half2*)&raw.x);
            float2 v1 = __half22float2(*(__half2*)&raw.y);
            fa.x += v0.x; fa.y += v0.y; fa.z += v1.x; fa.w += v1.y;
        }
        float inv = 1.f / fmaxf((float)(e - b), 1.f);
        s.x = fa.x * inv; s.y = fa.y * inv; s.z = fa.z * inv; s.w = fa.w * inv;
        o = outU + (size_t)d * CC + col;
    } else return;

    s.x += __shfl_xor_sync(~0u, s.x, 16);
    s.y += __shfl_xor_sync(~0u, s.y, 16);
    s.z += __shfl_xor_sync(~0u, s.z, 16);
    s.w += __shfl_xor_sync(~0u, s.w, 16);
    if (hf == 0) {
        float4 c = *(const float4*)o;
        *(float4*)o = make_float4(c.x + s.x, c.y + s.y, c.z + s.z, c.w + s.w);
    }
}

// ---------------- wave2: layer-2 duals + fused layer1-finalize chains ----------------
#define W2_B1 (U_BLK)
#define W2_B2 (U_BLK + S_BLK)
#define W2_B3 (U_BLK + S_BLK + W_BLK)
#define W2_TOT (U_BLK + S_BLK + W_BLK + 2)

__global__ void __launch_bounds__(256) wave2(
    const DualJobP d0, const DualJobP d1,
    const FBJobP f0, const FBJobP f1, const FBJobP f2)
{
    __shared__ uint32_t Whi[2][64][36], Wlo[2][64][36];
    int bx = blockIdx.x;
    if (bx < W2_B1)      { dual_body_p(d0, bx,          Whi[0], Wlo[0], Whi[1], Wlo[1]); return; }
    if (bx < W2_B2)      { dual_body_p(d1, bx - W2_B1,  Whi[0], Wlo[0], Whi[1], Wlo[1]); return; }
    if (bx < W2_B3)      { fb_body_p(f0, bx - W2_B2,    Whi[0], Wlo[0]); return; }
    if (bx == W2_B3)     { fb_body_p(f1, 0,             Whi[0], Wlo[0]); return; }
    fb_body_p(f2, 0, Whi[0], Wlo[0]);
}

// ---------------- classifier ----------------
__global__ void dot_score(const float* __restrict__ xu, const float* __restrict__ xs,
                          const int* __restrict__ ui, const int* __restrict__ si,
                          float* __restrict__ out, int E) {
    int gid = blockIdx.x * blockDim.x + threadIdx.x;
    int e = gid >> 4;
    int j = (gid & 15) << 2;
    int ec = (e < E) ? e : (E - 1);
    float4 a = *(const float4*)(xu + (size_t)ui[ec] * CC + j);
    float4 b = *(const float4*)(xs + (size_t)si[ec] * CC + j);
    float d = a.x*b.x + a.y*b.y + a.z*b.z + a.w*b.w;
    d += __shfl_xor_sync(0xffffffffu, d, 1);
    d += __shfl_xor_sync(0xffffffffu, d, 2);
    d += __shfl_xor_sync(0xffffffffu, d, 4);
    d += __shfl_xor_sync(0xffffffffu, d, 8);
    if ((gid & 15) == 0 && e < E) out[e] = d;
}

static inline int cdiv(int a, int b) { return (a + b - 1) / b; }

extern "C" void kernel_launch(void* const* d_in, const int* in_sizes, int n_in,
                              void* d_out, int out_size)
{
    const float* reviews  = (const float*)d_in[0];
    const float* overview = (const float*)d_in[1];
    const float* g_emb    = (const float*)d_in[2];
    const float* w_emb    = (const float*)d_in[3];
    const float* t_emb    = (const float*)d_in[4];
    const float* Wu  = (const float*)d_in[5];
    const float* bu  = (const float*)d_in[6];
    const float* Wsw = (const float*)d_in[7];
    const float* bs  = (const float*)d_in[8];
    const float* Wl1 = (const float*)d_in[9];
    const float* bl1 = (const float*)d_in[10];
    const float* Wr1 = (const float*)d_in[11];
    const float* Wl2 = (const float*)d_in[12];
    const float* bl2 = (const float*)d_in[13];
    const float* Wr2 = (const float*)d_in[14];
    const int* e_u2s = (const int*)d_in[15];
    const int* e_g2s = (const int*)d_in[16];
    const int* e_w2s = (const int*)d_in[17];
    const int* e_t2s = (const int*)d_in[18];
    const int* eli   = (const int*)d_in[19];
    float* out = (float*)d_out;

    int *cnt,*off,*csum,*csr;
    float *agg,*xs,*yu,*ys,*xu2,*xs2,*xwp,*xgp,*xtp;
    __half *tU,*tS,*tG,*tW,*tT,*tU2,*tS2,*tG2,*tW2,*tT2;
    float *blS1,*blS2;
    cudaGetSymbolAddress((void**)&cnt,  g_cnt);
    cudaGetSymbolAddress((void**)&off,  g_off);
    cudaGetSymbolAddress((void**)&csum, g_csum);
    cudaGetSymbolAddress((void**)&csr,  g_csr);
    cudaGetSymbolAddress((void**)&agg,  g_agg);
    cudaGetSymbolAddress((void**)&xs,   g_xs);
    cudaGetSymbolAddress((void**)&yu,   g_yu);
    cudaGetSymbolAddress((void**)&ys,   g_ys);
    cudaGetSymbolAddress((void**)&xu2,  g_xu2);
    cudaGetSymbolAddress((void**)&xs2,  g_xs2);
    cudaGetSymbolAddress((void**)&tU,   g_tU);
    cudaGetSymbolAddress((void**)&tS,   g_tS);
    cudaGetSymbolAddress((void**)&tG,   g_tG);
    cudaGetSymbolAddress((void**)&tW,   g_tW);
    cudaGetSymbolAddress((void**)&tT,   g_tT);
    cudaGetSymbolAddress((void**)&tU2,  g_tU2);
    cudaGetSymbolAddress((void**)&tS2,  g_tS2);
    cudaGetSymbolAddress((void**)&tG2,  g_tG2);
    cudaGetSymbolAddress((void**)&tW2,  g_tW2);
    cudaGetSymbolAddress((void**)&tT2,  g_tT2);
    cudaGetSymbolAddress((void**)&xwp,  g_xwp);
    cudaGetSymbolAddress((void**)&xgp,  g_xgp);
    cudaGetSymbolAddress((void**)&xtp,  g_xtp);
    cudaGetSymbolAddress((void**)&blS1, g_blS1);
    cudaGetSymbolAddress((void**)&blS2, g_blS2);

    int* cur = cnt + CNT_TOT;
    const int W44 = CC*CC;

    // ---- init ----
    cudaMemsetAsync(cnt, 0, (CNT_TOT + N_SCAN) * sizeof(int));
    cudaMemsetAsync(agg, 0, AGG_TOT * sizeof(float));

    // ---- launch 1: small duals (float W) + weight preconversion + degree count ----
    {
        DualJob jw = { w_emb, Wl1 + 4*W44, tW, Wr1 + 5*W44, bl1 + 5*CC, xwp, NW, 0 };
        DualJob jg = { g_emb, Wl1 + 2*W44, tG, Wr1 + 3*W44, bl1 + 3*CC, xgp, NG, 0 };
        DualJob jt = { t_emb, Wl1 + 6*W44, tT, Wr1 + 7*W44, bl1 + 7*CC, xtp, NT, 0 };
        prep_deg_duals<<<PD_TOT, 256>>>(jw, jg, jt, Wu, Wsw, Wl1, bl1, Wr1, Wl2, bl2, Wr2,
                                        e_u2s, e_g2s, e_w2s, e_t2s, cnt);
    }

    // ---- scans ----
    scan1<<<NCHUNK, 256>>>(cnt, csum);
    scan23<<<NCHUNK, 256>>>(cnt, csum, off);

    // ---- p0: big transforms (occ-3, double-buffered preconverted W) + chains + fill_csr ----
    {
        P0Job ju = { reviews,  PRE_WU,  bu, nullptr,
                     PREK(9),  bl1 + 1*CC, yu,      // yu_pre = xu@Wr1_1 + bl1_1
                     PREK(0),  tU, NU };            // tU = xu@Wl1_0
        P0Job js = { overview, PRE_WSW, bs, xs,
                     PREK(32), blS1, ys,            // ys_pre = xs@WrS1 + blS1
                     PREK(1),  tS, NS };            // tS = xs@Wl1_1
        p0_mega<<<P0_TOT, 256>>>(ju, js, e_u2s, e_g2s, e_w2s, e_t2s, off, cur, csr);
    }

    // ---- gather 1 + s->g/w/t scatter (fused) ----
    {
        ScatJob s0 = { xs, e_g2s + E_GS, e_g2s, agg + AGG_G };
        ScatJob s1 = { xs, e_w2s + E_WS, e_w2s, agg + AGG_W };
        ScatJob s2 = { xs, e_t2s + E_TS, e_t2s, agg + AGG_T };
        gather_scatter<<<GATH_BLK + SCAT_BLK, 256>>>(tU, tS, tG, tW, tT, ys, yu,
                                                     off, csr, s0, s1, s2);
    }

    // ---- wave2 ----
    {
        DualJobP d0 = { yu, PREK(16), tU2, PREK(25), bl2 + 1*CC, xu2, NU, 1 };
        DualJobP d1 = { ys, PREK(17), tS2, PREK(33), blS2,       xs2, NS, 1 };
        FBJobP f0 = { agg + AGG_W, PREK(5), xwp, cnt + CNT_W, PREK(20), tW2, NW };
        FBJobP f1 = { agg + AGG_G, PREK(3), xgp, cnt + CNT_G, PREK(18), tG2, NG };
        FBJobP f2 = { agg + AGG_T, PREK(7), xtp, cnt + CNT_T, PREK(22), tT2, NT };
        wave2<<<W2_TOT, 256>>>(d0, d1, f0, f1, f2);
    }

    // ---- gather 2 ----
    {
        ScatJob sd = { nullptr, nullptr, nullptr, nullptr };
        gather_scatter<<<GATH_BLK, 256>>>(tU2, tS2, tG2, tW2, tT2, xs2, xu2,
                                          off, csr, sd, sd, sd);
    }

    // ---- classifier ----
    dot_score<<<E_LI*16/256, 256>>>(xu2, xs2, eli, eli + E_LI, out, E_LI);
}

// round 13
// speedup vs baseline: 1.0435x; 1.0027x over previous
#include <cuda_runtime.h>
#include <cuda_bf16.h>
#include <cuda_fp16.h>
#include <cstdint>

#define NU 100000
#define NS 50000
#define NG 50
#define NW 20000
#define NT 10
#define CC 64
#define FF 384
#define E_US 1000000
#define E_GS 150000
#define E_WS 50000
#define E_TS 50000
#define E_LI 200000

#define CNT_U   0
#define CNT_SU  (NU)
#define CNT_SG  (NU+NS)
#define CNT_SW  (NU+2*NS)
#define CNT_ST  (NU+3*NS)
#define CNT_G   (NU+4*NS)
#define CNT_W   (NU+4*NS+NG)
#define CNT_T   (NU+4*NS+NG+NW)
#define CNT_TOT (NU+4*NS+NG+NW+NT)

#define N_SCAN  (NU + 4*NS)
#define CSR_TOT (2*E_US + E_GS + E_WS + E_TS)
#define CHUNK   1024
#define NCHUNK  ((N_SCAN + CHUNK - 1) / CHUNK)

#define AGG_G 0
#define AGG_W ((size_t)NG*CC)
#define AGG_T ((size_t)(NG+NW)*CC)
#define AGG_TOT ((size_t)(NG+NW+NT)*CC)

#define U_BLK 782
#define S_BLK 391
#define W_BLK 157

// ---- preconverted weight store (bf16 hi/lo pairs, [64][K/2] u32 per matrix) ----
#define PRE_WU  0
#define PRE_WSW 12288
#define PREK(i) (24576 + (i)*2048)
// Wl1_i -> PREK(i), Wr1_i -> PREK(8+i), Wl2_i -> PREK(16+i), Wr2_i -> PREK(24+i),
// WrS1 -> PREK(32), WrS2 -> PREK(33)
#define PRE_SZ  (24576 + 34*2048)

// ---------------- scratch ----------------
__device__ int   g_cnt[CNT_TOT + N_SCAN];
__device__ int   g_off[N_SCAN + 1];
__device__ int   g_csum[NCHUNK];
__device__ int   g_csr[CSR_TOT];
__device__ float g_agg[AGG_TOT];
__device__ uint32_t g_whi[PRE_SZ], g_wlo[PRE_SZ];

__device__ float g_xs[NS*CC];
__device__ float g_yu[NU*CC], g_ys[NS*CC];
__device__ float g_xu2[NU*CC], g_xs2[NS*CC];
__device__ __half g_tU[NU*CC], g_tS[NS*CC], g_tG[NG*CC], g_tW[NW*CC], g_tT[NT*CC];
__device__ __half g_tU2[NU*CC], g_tS2[NS*CC], g_tG2[NG*CC], g_tW2[NW*CC], g_tT2[NT*CC];
__device__ float g_xwp[NW*CC], g_xgp[NG*CC], g_xtp[NT*CC];
__device__ float g_blS1[CC], g_blS2[CC];

// ---------------- bf16 split helpers ----------------
__device__ __forceinline__ void split2(float x, float y, uint32_t& hi, uint32_t& lo) {
    __nv_bfloat162 h = __floats2bfloat162_rn(x, y);
    float2 hf = __bfloat1622float2(h);
    __nv_bfloat162 l = __floats2bfloat162_rn(x - hf.x, y - hf.y);
    hi = *(uint32_t*)&h;
    lo = *(uint32_t*)&l;
}
__device__ __forceinline__ void mma16(float* d, const uint32_t* a, uint32_t b0, uint32_t b1) {
    asm("mma.sync.aligned.m16n8k16.row.col.f32.bf16.bf16.f32 "
        "{%0,%1,%2,%3}, {%4,%5,%6,%7}, {%8,%9}, {%0,%1,%2,%3};"
        : "+f"(d[0]), "+f"(d[1]), "+f"(d[2]), "+f"(d[3])
        : "r"(a[0]), "r"(a[1]), "r"(a[2]), "r"(a[3]), "r"(b0), "r"(b1));
}

// float staging (only for launch-1 duals, before preconversion is ready)
__device__ __forceinline__ void stage_w(const float* W, int ld, int k0,
                                        uint32_t (*Whi)[36], uint32_t (*Wlo)[36], int tid) {
#pragma unroll
    for (int i = tid; i < 64 * 32; i += 256) {
        int n = i >> 5, kp = i & 31;
        float2 w = *(const float2*)(W + (size_t)n * ld + k0 + 2 * kp);
        split2(w.x, w.y, Whi[n][kp], Wlo[n][kp]);
    }
}

// preconverted staging: plain copies
__device__ __forceinline__ void stage_pre(int woff, int Kpairs, int kp0,
                                          uint32_t (*Whi)[36], uint32_t (*Wlo)[36], int tid) {
    const uint32_t* hi = g_whi + woff;
    const uint32_t* lo = g_wlo + woff;
#pragma unroll
    for (int i = tid; i < 64 * 32; i += 256) {
        int n = i >> 5, kp = i & 31;
        Whi[n][kp] = hi[n * Kpairs + kp0 + kp];
        Wlo[n][kp] = lo[n * Kpairs + kp0 + kp];
    }
}

__device__ __forceinline__ void mma_shared(float (*acc)[4], const uint32_t* ah, const uint32_t* al,
                                           const uint32_t (*Whi)[36], const uint32_t (*Wlo)[36],
                                           int ks, int g, int tg) {
#pragma unroll
    for (int j = 0; j < 8; j++) {
        uint32_t bh0 = Whi[j*8+g][ks*8+tg], bh1 = Whi[j*8+g][ks*8+tg+4];
        uint32_t bl0 = Wlo[j*8+g][ks*8+tg], bl1 = Wlo[j*8+g][ks*8+tg+4];
        mma16(acc[j], ah, bh0, bh1);
        mma16(acc[j], al, bh0, bh1);
        mma16(acc[j], ah, bl0, bl1);
    }
}

__device__ __forceinline__ void load_afrag(const float* A0, const float* A1, int kk, int relu,
                                           uint32_t* ah, uint32_t* al) {
    float2 a00 = *(const float2*)(A0 + kk);
    float2 a10 = *(const float2*)(A1 + kk);
    float2 a01 = *(const float2*)(A0 + kk + 8);
    float2 a11 = *(const float2*)(A1 + kk + 8);
    if (relu) {
        a00.x=fmaxf(a00.x,0.f); a00.y=fmaxf(a00.y,0.f);
        a10.x=fmaxf(a10.x,0.f); a10.y=fmaxf(a10.y,0.f);
        a01.x=fmaxf(a01.x,0.f); a01.y=fmaxf(a01.y,0.f);
        a11.x=fmaxf(a11.x,0.f); a11.y=fmaxf(a11.y,0.f);
    }
    split2(a00.x, a00.y, ah[0], al[0]);
    split2(a10.x, a10.y, ah[1], al[1]);
    split2(a01.x, a01.y, ah[2], al[2]);
    split2(a11.x, a11.y, ah[3], al[3]);
}

// register-chained GEMM using preconverted weights (L1-resident)
__device__ __forceinline__ void chain_pre(const float (*e)[4], int woff,
                                          float (*a2)[4], int g, int tg) {
    const uint32_t* whi = g_whi + woff;
    const uint32_t* wlo = g_wlo + woff;
#pragma unroll
    for (int jj = 0; jj < 4; jj++) {
        uint32_t ah[4], al[4];
        split2(e[2*jj][0],   e[2*jj][1],   ah[0], al[0]);
        split2(e[2*jj][2],   e[2*jj][3],   ah[1], al[1]);
        split2(e[2*jj+1][0], e[2*jj+1][1], ah[2], al[2]);
        split2(e[2*jj+1][2], e[2*jj+1][3], ah[3], al[3]);
#pragma unroll
        for (int j = 0; j < 8; j++) {
            int r = (j*8+g)*32 + 8*jj + tg;
            uint32_t bh0 = whi[r], bh1 = whi[r+4];
            uint32_t bl0 = wlo[r], bl1 = wlo[r+4];
            mma16(a2[j], ah, bh0, bh1);
            mma16(a2[j], al, bh0, bh1);
            mma16(a2[j], ah, bl0, bl1);
        }
    }
}

__device__ __forceinline__ void store_frag(const float (*acc)[4], const float* bias,
                                           float* out, int mr0, int M, int tg) {
#pragma unroll
    for (int j = 0; j < 8; j++) {
        int n = j*8 + 2*tg;
        float b0 = bias ? bias[n] : 0.f, b1 = bias ? bias[n+1] : 0.f;
        if (mr0 < M)
            *(float2*)(out + (size_t)mr0*CC + n) = make_float2(acc[j][0]+b0, acc[j][1]+b1);
        if (mr0+8 < M)
            *(float2*)(out + (size_t)(mr0+8)*CC + n) = make_float2(acc[j][2]+b0, acc[j][3]+b1);
    }
}

__device__ __forceinline__ void store_frag_h(const float (*acc)[4], __half* out,
                                             int mr0, int M, int tg) {
#pragma unroll
    for (int j = 0; j < 8; j++) {
        int n = j*8 + 2*tg;
        if (mr0 < M)
            *(__half2*)(out + (size_t)mr0*CC + n) = __floats2half2_rn(acc[j][0], acc[j][1]);
        if (mr0+8 < M)
            *(__half2*)(out + (size_t)(mr0+8)*CC + n) = __floats2half2_rn(acc[j][2], acc[j][3]);
    }
}

// ---------------- job structs ----------------
struct DualJob {                  // float-weight variant (launch 1 only)
    const float* A; const float* W0; __half* o0;
    const float* W1; const float* b1; float* o1; int M; int relu_in;
};
struct DualJobP {                 // preconverted-weight variant
    const float* A; int w0; __half* o0;
    int w1; const float* b1; float* o1; int M; int relu_in;
};
struct FBJobP {
    const float* A; int w1; const float* accin; const int* cnt;
    int wc; __half* out; int M;
};
struct P0Job {
    const float* A; int wpre; const float* bias; float* xout;
    int wc0; const float* bc0; float* oc0;
    int wc1; __half* oc1;
    int M;
};
struct ScatJob { const float* x; const int* src; const int* dst; float* out; };

// ---------------- GEMM bodies ----------------
__device__ __forceinline__ void dual_body_f(const DualJob& jb, int bx,
                                            uint32_t (*WhiA)[36], uint32_t (*WloA)[36],
                                            uint32_t (*WhiB)[36], uint32_t (*WloB)[36]) {
    const int m0 = bx * 128;
    const int tid = threadIdx.x, wid = tid >> 5, lane = tid & 31;
    const int g = lane >> 2, tg = lane & 3;

    stage_w(jb.W0, CC, 0, WhiA, WloA, tid);
    stage_w(jb.W1, CC, 0, WhiB, WloB, tid);
    __syncthreads();

    float acc[2][8][4];
#pragma unroll
    for (int w = 0; w < 2; w++)
#pragma unroll
        for (int j = 0; j < 8; j++) { acc[w][j][0]=acc[w][j][1]=acc[w][j][2]=acc[w][j][3]=0.f; }

    const int mtop = jb.M - 1;
    const int mr0 = m0 + wid * 16 + g;
    const float* A0 = jb.A + (size_t)min(mr0,     mtop) * CC;
    const float* A1 = jb.A + (size_t)min(mr0 + 8, mtop) * CC;

#pragma unroll
    for (int ks = 0; ks < 4; ks++) {
        uint32_t ah[4], al[4];
        load_afrag(A0, A1, ks*16 + 2*tg, jb.relu_in, ah, al);
        mma_shared(acc[0], ah, al, WhiA, WloA, ks, g, tg);
        mma_shared(acc[1], ah, al, WhiB, WloB, ks, g, tg);
    }
    store_frag_h(acc[0], jb.o0, mr0, jb.M, tg);
    store_frag(acc[1], jb.b1, jb.o1, mr0, jb.M, tg);
}

__device__ __forceinline__ void dual_body_p(const DualJobP& jb, int bx,
                                            uint32_t (*WhiA)[36], uint32_t (*WloA)[36],
                                            uint32_t (*WhiB)[36], uint32_t (*WloB)[36]) {
    const int m0 = bx * 128;
    const int tid = threadIdx.x, wid = tid >> 5, lane = tid & 31;
    const int g = lane >> 2, tg = lane & 3;

    stage_pre(jb.w0, 32, 0, WhiA, WloA, tid);
    stage_pre(jb.w1, 32, 0, WhiB, WloB, tid);
    __syncthreads();

    float acc[2][8][4];
#pragma unroll
    for (int w = 0; w < 2; w++)
#pragma unroll
        for (int j = 0; j < 8; j++) { acc[w][j][0]=acc[w][j][1]=acc[w][j][2]=acc[w][j][3]=0.f; }

    const int mtop = jb.M - 1;
    const int mr0 = m0 + wid * 16 + g;
    const float* A0 = jb.A + (size_t)min(mr0,     mtop) * CC;
    const float* A1 = jb.A + (size_t)min(mr0 + 8, mtop) * CC;

#pragma unroll
    for (int ks = 0; ks < 4; ks++) {
        uint32_t ah[4], al[4];
        load_afrag(A0, A1, ks*16 + 2*tg, jb.relu_in, ah, al);
        mma_shared(acc[0], ah, al, WhiA, WloA, ks, g, tg);
        mma_shared(acc[1], ah, al, WhiB, WloB, ks, g, tg);
    }
    store_frag_h(acc[0], jb.o0, mr0, jb.M, tg);
    store_frag(acc[1], jb.b1, jb.o1, mr0, jb.M, tg);
}

__device__ __forceinline__ void fb_body_p(const FBJobP& jb, int bx,
                                          uint32_t (*Whi)[36], uint32_t (*Wlo)[36]) {
    const int m0 = bx * 128;
    const int tid = threadIdx.x, wid = tid >> 5, lane = tid & 31;
    const int g = lane >> 2, tg = lane & 3;

    stage_pre(jb.w1, 32, 0, Whi, Wlo, tid);
    __syncthreads();

    float acc1[8][4];
#pragma unroll
    for (int j = 0; j < 8; j++) { acc1[j][0]=acc1[j][1]=acc1[j][2]=acc1[j][3]=0.f; }

    const int mtop = jb.M - 1;
    const int mr0 = m0 + wid * 16 + g;
    const int r0 = min(mr0, mtop), r1 = min(mr0 + 8, mtop);
    const float* A0 = jb.A + (size_t)r0 * CC;
    const float* A1 = jb.A + (size_t)r1 * CC;

#pragma unroll
    for (int ks = 0; ks < 4; ks++) {
        uint32_t ah[4], al[4];
        load_afrag(A0, A1, ks*16 + 2*tg, 0, ah, al);
        mma_shared(acc1, ah, al, Whi, Wlo, ks, g, tg);
    }

    const float s0 = 1.f / fmaxf((float)jb.cnt[r0], 1.f);
    const float s1 = 1.f / fmaxf((float)jb.cnt[r1], 1.f);
#pragma unroll
    for (int j = 0; j < 8; j++) {
        int n = j*8 + 2*tg;
        float2 c0 = *(const float2*)(jb.accin + (size_t)r0 * CC + n);
        float2 c1 = *(const float2*)(jb.accin + (size_t)r1 * CC + n);
        acc1[j][0] = fmaxf(acc1[j][0]*s0 + c0.x, 0.f);
        acc1[j][1] = fmaxf(acc1[j][1]*s0 + c0.y, 0.f);
        acc1[j][2] = fmaxf(acc1[j][2]*s1 + c1.x, 0.f);
        acc1[j][3] = fmaxf(acc1[j][3]*s1 + c1.y, 0.f);
    }

    float a2[8][4];
#pragma unroll
    for (int j = 0; j < 8; j++) { a2[j][0]=a2[j][1]=a2[j][2]=a2[j][3]=0.f; }
    chain_pre(acc1, jb.wc, a2, g, tg);
    store_frag_h(a2, jb.out, mr0, jb.M, tg);
}

// ---------------- launch 1: small duals + weight prep/preconvert + deg count ----
#define PD_PREP (W_BLK + 2)
#define PD_CONV (PD_PREP + 16)
#define PD_NCONV 64
#define PD_DEG  (PD_CONV + PD_NCONV)
#define PD_DEGBLK 512
#define PD_TOT  (PD_DEG + PD_DEGBLK)

__global__ void __launch_bounds__(256) prep_deg_duals(
    const DualJob jw, const DualJob jg, const DualJob jt,
    const float* __restrict__ Wu, const float* __restrict__ Wsw,
    const float* __restrict__ Wl1, const float* __restrict__ bl1,
    const float* __restrict__ Wr1,
    const float* __restrict__ Wl2, const float* __restrict__ bl2,
    const float* __restrict__ Wr2,
    const int* __restrict__ u2s, const int* __restrict__ g2s,
    const int* __restrict__ w2s, const int* __restrict__ t2s,
    int* __restrict__ cnt)
{
    __shared__ uint32_t Whi[2][64][36], Wlo[2][64][36];
    int bx = blockIdx.x;
    if (bx < W_BLK)     { dual_body_f(jw, bx, Whi[0], Wlo[0], Whi[1], Wlo[1]); return; }
    if (bx == W_BLK)    { dual_body_f(jg, 0,  Whi[0], Wlo[0], Whi[1], Wlo[1]); return; }
    if (bx == W_BLK+1)  { dual_body_f(jt, 0,  Whi[0], Wlo[0], Whi[1], Wlo[1]); return; }
    if (bx < PD_CONV) {
        int i = (bx - PD_PREP) * 256 + threadIdx.x;
        if (i < 2048) {
            float x1=0.f,y1=0.f,x2=0.f,y2=0.f;
#pragma unroll
            for (int m = 0; m < 4; m++) {
                const float* w1 = Wr1 + (size_t)(2*m)*4096;
                const float* w2 = Wr2 + (size_t)(2*m)*4096;
                x1 += w1[2*i]; y1 += w1[2*i+1];
                x2 += w2[2*i]; y2 += w2[2*i+1];
            }
            split2(x1, y1, g_whi[PREK(32)+i], g_wlo[PREK(32)+i]);
            split2(x2, y2, g_whi[PREK(33)+i], g_wlo[PREK(33)+i]);
        }
        if (i < CC) {
            g_blS1[i] = bl1[i] + bl1[2*CC+i] + bl1[4*CC+i] + bl1[6*CC+i];
            g_blS2[i] = bl2[i] + bl2[2*CC+i] + bl2[4*CC+i] + bl2[6*CC+i];
        }
        return;
    }
    if (bx < PD_DEG) {
        const float* src[6] = { Wu, Wsw, Wl1, Wr1, Wl2, Wr2 };
        const int dst[6]    = { PRE_WU, PRE_WSW, PREK(0), PREK(8), PREK(16), PREK(24) };
        const int end[6]    = { 12288, 24576, 40960, 57344, 73728, 90112 };
        const int stride = PD_NCONV * 256;
        for (int i = (bx - PD_CONV) * 256 + threadIdx.x; i < 90112; i += stride) {
            int s = 0;
            while (i >= end[s]) s++;
            int local = i - (s ? end[s-1] : 0);
            float2 w = *(const float2*)(src[s] + 2*(size_t)local);
            split2(w.x, w.y, g_whi[dst[s]+local], g_wlo[dst[s]+local]);
        }
        return;
    }
    const int stride = PD_DEGBLK * 256;
    int base = (bx - PD_DEG) * 256 + threadIdx.x;
    for (int i = base; i < E_US; i += stride) {
        atomicAdd(cnt + CNT_U  + u2s[i], 1);
        atomicAdd(cnt + CNT_SU + u2s[E_US + i], 1);
    }
    for (int i = base; i < E_GS; i += stride) {
        atomicAdd(cnt + CNT_G  + g2s[i], 1);
        atomicAdd(cnt + CNT_SG + g2s[E_GS + i], 1);
    }
    for (int i = base; i < E_WS; i += stride) {
        atomicAdd(cnt + CNT_W  + w2s[i], 1);
        atomicAdd(cnt + CNT_SW + w2s[E_WS + i], 1);
    }
    for (int i = base; i < E_TS; i += stride) {
        atomicAdd(cnt + CNT_T  + t2s[i], 1);
        atomicAdd(cnt + CNT_ST + t2s[E_TS + i], 1);
    }
}

// ---------------- scans ----------------
__global__ void scan1(const int* __restrict__ cnt, int* __restrict__ csum) {
    __shared__ int sh[8];
    int c = blockIdx.x, t = threadIdx.x, base = c * CHUNK;
    int s = 0;
#pragma unroll
    for (int q = 0; q < 4; q++) {
        int idx = base + t*4 + q;
        if (idx < N_SCAN) s += cnt[idx];
    }
    for (int o = 16; o; o >>= 1) s += __shfl_down_sync(~0u, s, o);
    if ((t & 31) == 0) sh[t >> 5] = s;
    __syncthreads();
    if (t == 0) { int tot = 0; for (int w = 0; w < 8; w++) tot += sh[w]; csum[c] = tot; }
}

__global__ void scan23(const int* __restrict__ cnt, const int* __restrict__ csum,
                       int* __restrict__ off) {
    __shared__ int sh[8], sh2[8], basev;
    int c = blockIdx.x, t = threadIdx.x;
    int lane = t & 31, w = t >> 5;

    int p = 0;
    for (int i = t; i < c; i += 256) p += csum[i];
    for (int o = 16; o; o >>= 1) p += __shfl_down_sync(~0u, p, o);
    if (lane == 0) sh2[w] = p;
    __syncthreads();
    if (t == 0) { int a = 0; for (int i = 0; i < 8; i++) a += sh2[i]; basev = a; }
    __syncthreads();
    const int cbase = basev;

    int base = c * CHUNK;
    int v[4]; int s = 0;
#pragma unroll
    for (int q = 0; q < 4; q++) {
        int idx = base + t*4 + q;
        v[q] = (idx < N_SCAN) ? cnt[idx] : 0;
        s += v[q];
    }
    int incl = s;
    for (int o = 1; o < 32; o <<= 1) {
        int x = __shfl_up_sync(~0u, incl, o);
        if (lane >= o) incl += x;
    }
    if (lane == 31) sh[w] = incl;
    __syncthreads();
    if (t == 0) { int a = 0; for (int i = 0; i < 8; i++) { int x = sh[i]; sh[i] = a; a += x; } }
    __syncthreads();
    int excl = incl - s + sh[w] + cbase;
#pragma unroll
    for (int q = 0; q < 4; q++) {
        int idx = base + t*4 + q;
        if (idx < N_SCAN) off[idx] = excl;
        excl += v[q];
        if (idx == N_SCAN - 1) off[N_SCAN] = excl;
    }
}

// ---------------- p0 mega: M=128/block, occ-3 forced, packed 1-D ----------------
#define P0_JU   U_BLK                     // 782
#define P0_FILL (U_BLK + S_BLK)           // 1173
#define P0_FILLBLK 3907
#define P0_TOT  (P0_FILL + P0_FILLBLK)

__global__ void __launch_bounds__(256, 3) p0_mega(
    const P0Job j0, const P0Job j1,
    const int* __restrict__ u2s, const int* __restrict__ g2s,
    const int* __restrict__ w2s, const int* __restrict__ t2s,
    const int* __restrict__ off, int* __restrict__ cur, int* __restrict__ csr)
{
    __shared__ uint32_t Whi[2][64][36], Wlo[2][64][36];
    int bx = blockIdx.x;
    if (bx >= P0_FILL) {
        int i = (bx - P0_FILL) * 256 + threadIdx.x;
        if (i < E_US) {
            int u = u2s[i], s = u2s[E_US + i];
            int n0 = CNT_SU + s;
            csr[off[n0] + atomicAdd(cur + n0, 1)] = u;
            int n1 = CNT_U + u;
            csr[off[n1] + atomicAdd(cur + n1, 1)] = s;
        }
        if (i < E_GS) {
            int gg = g2s[i], s = g2s[E_GS + i];
            int n = CNT_SG + s;
            csr[off[n] + atomicAdd(cur + n, 1)] = gg;
        }
        if (i < E_WS) {
            int ww = w2s[i], s = w2s[E_WS + i];
            int n = CNT_SW + s;
            csr[off[n] + atomicAdd(cur + n, 1)] = ww;
        }
        if (i < E_TS) {
            int tt = t2s[i], s = t2s[E_TS + i];
            int n = CNT_ST + s;
            csr[off[n] + atomicAdd(cur + n, 1)] = tt;
        }
        return;
    }
    const P0Job jb = (bx >= P0_JU) ? j1 : j0;
    const int m0 = ((bx >= P0_JU) ? bx - P0_JU : bx) * 128;

    const int tid = threadIdx.x, wid = tid >> 5, lane = tid & 31;
    const int g = lane >> 2, tg = lane & 3;

    float acc1[8][4];
#pragma unroll
    for (int j = 0; j < 8; j++) { acc1[j][0]=acc1[j][1]=acc1[j][2]=acc1[j][3]=0.f; }

    const int mtop = jb.M - 1;
    const int mr0 = m0 + wid * 16 + g;
    const float* A0 = jb.A + (size_t)min(mr0,     mtop) * FF;
    const float* A1 = jb.A + (size_t)min(mr0 + 8, mtop) * FF;

    stage_pre(jb.wpre, 192, 0, Whi[0], Wlo[0], tid);
    __syncthreads();

#pragma unroll
    for (int t = 0; t < 6; t++) {
        const int cb = t & 1;
        if (t < 5) stage_pre(jb.wpre, 192, (t+1)*32, Whi[cb^1], Wlo[cb^1], tid);
#pragma unroll
        for (int ks = 0; ks < 4; ks++) {
            uint32_t ah[4], al[4];
            load_afrag(A0, A1, t*64 + ks*16 + 2*tg, 0, ah, al);
            mma_shared(acc1, ah, al, Whi[cb], Wlo[cb], ks, g, tg);
        }
        __syncthreads();
    }

    // bias -> acc1 is the transformed feature x
#pragma unroll
    for (int j = 0; j < 8; j++) {
        int n = j*8 + 2*tg;
        float b0 = jb.bias[n], b1 = jb.bias[n+1];
        acc1[j][0] += b0; acc1[j][1] += b1;
        acc1[j][2] += b0; acc1[j][3] += b1;
    }
    if (jb.xout) store_frag(acc1, nullptr, jb.xout, mr0, jb.M, tg);

    // sequential chains (reuse a2 registers)
    float a2[8][4];
#pragma unroll
    for (int j = 0; j < 8; j++) { a2[j][0]=a2[j][1]=a2[j][2]=a2[j][3]=0.f; }
    chain_pre(acc1, jb.wc0, a2, g, tg);
    store_frag(a2, jb.bc0, jb.oc0, mr0, jb.M, tg);

#pragma unroll
    for (int j = 0; j < 8; j++) { a2[j][0]=a2[j][1]=a2[j][2]=a2[j][3]=0.f; }
    chain_pre(acc1, jb.wc1, a2, g, tg);
    store_frag_h(a2, jb.oc1, mr0, jb.M, tg);
}

// ---------------- gather (+optional fused scatter blocks) ----------------
#define GATH_BLK 18750
#define SCAT_E   (E_GS + E_WS + E_TS)
#define SCAT_BLK ((SCAT_E * 8 + 255) / 256)

__global__ void __launch_bounds__(256) gather_scatter(
    const __half* __restrict__ tU, const __half* __restrict__ tS,
    const __half* __restrict__ tG, const __half* __restrict__ tW, const __half* __restrict__ tT,
    float* __restrict__ outS, float* __restrict__ outU,
    const int* __restrict__ off, const int* __restrict__ csr,
    const ScatJob s0, const ScatJob s1, const ScatJob s2)
{
    int bx = blockIdx.x;
    if (bx >= GATH_BLK) {
        int gid = (bx - GATH_BLK) * 256 + threadIdx.x;
        int ge = gid >> 3;
        if (ge >= SCAT_E) return;
        int part = gid & 7;
        const ScatJob jb = (ge < E_GS) ? s0 : (ge < E_GS + E_WS ? s1 : s2);
        int e = (ge < E_GS) ? ge : (ge < E_GS + E_WS ? ge - E_GS : ge - E_GS - E_WS);
        int s = jb.src[e], d = jb.dst[e];
        const float4* xp = (const float4*)(jb.x + (size_t)s * CC);
        float4*       op = (float4*)(jb.out + (size_t)d * CC);
        atomicAdd(op + part,     xp[part]);
        atomicAdd(op + part + 8, xp[part + 8]);
        return;
    }
    int gw = (bx * 256 + threadIdx.x) >> 5;
    int lane = threadIdx.x & 31;
    int hf = lane >> 4;
    int col = (lane & 15) * 4;
    float4 s = make_float4(0.f, 0.f, 0.f, 0.f);
    float* o;

    if (gw < NS) {
        const int d = gw;
        const int node[4] = { CNT_SU + d, CNT_SG + d, CNT_SW + d, CNT_ST + d };
        const __half* buf[4] = { tU, tG, tW, tT };
#pragma unroll
        for (int f = 0; f < 4; f++) {
            int b = off[node[f]], e = off[node[f] + 1];
            float4 fa = make_float4(0.f, 0.f, 0.f, 0.f);
#pragma unroll 2
            for (int i = b + hf; i < e; i += 2) {
                int src = csr[i];
                uint2 raw = *(const uint2*)(buf[f] + (size_t)src * CC + col);
                float2 v0 = __half22float2(*(__half2*)&raw.x);
                float2 v1 = __half22float2(*(__half2*)&raw.y);
                fa.x += v0.x; fa.y += v0.y; fa.z += v1.x; fa.w += v1.y;
            }
            float inv = 1.f / fmaxf((float)(e - b), 1.f);
            s.x += fa.x * inv; s.y += fa.y * inv; s.z += fa.z * inv; s.w += fa.w * inv;
        }
        o = outS + (size_t)d * CC + col;
    } else if (gw < NS + NU) {
        const int d = gw - NS;
        int b = off[CNT_U + d], e = off[CNT_U + d + 1];
        float4 fa = make_float4(0.f, 0.f, 0.f, 0.f);
#pragma unroll 2
        for (int i = b + hf; i < e; i += 2) {
            int src = csr[i];
            uint2 raw = *(const uint2*)(tS + (size_t)src * CC + col);
            float2 v0 = __half22float2(*(__half2*)&raw.x);
            float2 v1 = __half22float2(*(__half2*)&raw.y);
            fa.x += v0.x; fa.y += v0.y; fa.z += v1.x; fa.w += v1.y;
        }
        float inv = 1.f / fmaxf((float)(e - b), 1.f);
        s.x = fa.x * inv; s.y = fa.y * inv; s.z = fa.z * inv; s.w = fa.w * inv;
        o = outU + (size_t)d * CC + col;
    } else return;

    s.x += __shfl_xor_sync(~0u, s.x, 16);
    s.y += __shfl_xor_sync(~0u, s.y, 16);
    s.z += __shfl_xor_sync(~0u, s.z, 16);
    s.w += __shfl_xor_sync(~0u, s.w, 16);
    if (hf == 0) {
        float4 c = *(const float4*)o;
        *(float4*)o = make_float4(c.x + s.x, c.y + s.y, c.z + s.z, c.w + s.w);
    }
}

// ---------------- wave2: layer-2 duals + fused layer1-finalize chains ----------------
#define W2_B1 (U_BLK)
#define W2_B2 (U_BLK + S_BLK)
#define W2_B3 (U_BLK + S_BLK + W_BLK)
#define W2_TOT (U_BLK + S_BLK + W_BLK + 2)

__global__ void __launch_bounds__(256) wave2(
    const DualJobP d0, const DualJobP d1,
    const FBJobP f0, const FBJobP f1, const FBJobP f2)
{
    __shared__ uint32_t Whi[2][64][36], Wlo[2][64][36];
    int bx = blockIdx.x;
    if (bx < W2_B1)      { dual_body_p(d0, bx,          Whi[0], Wlo[0], Whi[1], Wlo[1]); return; }
    if (bx < W2_B2)      { dual_body_p(d1, bx - W2_B1,  Whi[0], Wlo[0], Whi[1], Wlo[1]); return; }
    if (bx < W2_B3)      { fb_body_p(f0, bx - W2_B2,    Whi[0], Wlo[0]); return; }
    if (bx == W2_B3)     { fb_body_p(f1, 0,             Whi[0], Wlo[0]); return; }
    fb_body_p(f2, 0, Whi[0], Wlo[0]);
}

// ---------------- classifier ----------------
__global__ void dot_score(const float* __restrict__ xu, const float* __restrict__ xs,
                          const int* __restrict__ ui, const int* __restrict__ si,
                          float* __restrict__ out, int E) {
    int gid = blockIdx.x * blockDim.x + threadIdx.x;
    int e = gid >> 4;
    int j = (gid & 15) << 2;
    int ec = (e < E) ? e : (E - 1);
    float4 a = *(const float4*)(xu + (size_t)ui[ec] * CC + j);
    float4 b = *(const float4*)(xs + (size_t)si[ec] * CC + j);
    float d = a.x*b.x + a.y*b.y + a.z*b.z + a.w*b.w;
    d += __shfl_xor_sync(0xffffffffu, d, 1);
    d += __shfl_xor_sync(0xffffffffu, d, 2);
    d += __shfl_xor_sync(0xffffffffu, d, 4);
    d += __shfl_xor_sync(0xffffffffu, d, 8);
    if ((gid & 15) == 0 && e < E) out[e] = d;
}

static inline int cdiv(int a, int b) { return (a + b - 1) / b; }

extern "C" void kernel_launch(void* const* d_in, const int* in_sizes, int n_in,
                              void* d_out, int out_size)
{
    const float* reviews  = (const float*)d_in[0];
    const float* overview = (const float*)d_in[1];
    const float* g_emb    = (const float*)d_in[2];
    const float* w_emb    = (const float*)d_in[3];
    const float* t_emb    = (const float*)d_in[4];
    const float* Wu  = (const float*)d_in[5];
    const float* bu  = (const float*)d_in[6];
    const float* Wsw = (const float*)d_in[7];
    const float* bs  = (const float*)d_in[8];
    const float* Wl1 = (const float*)d_in[9];
    const float* bl1 = (const float*)d_in[10];
    const float* Wr1 = (const float*)d_in[11];
    const float* Wl2 = (const float*)d_in[12];
    const float* bl2 = (const float*)d_in[13];
    const float* Wr2 = (const float*)d_in[14];
    const int* e_u2s = (const int*)d_in[15];
    const int* e_g2s = (const int*)d_in[16];
    const int* e_w2s = (const int*)d_in[17];
    const int* e_t2s = (const int*)d_in[18];
    const int* eli   = (const int*)d_in[19];
    float* out = (float*)d_out;

    int *cnt,*off,*csum,*csr;
    float *agg,*xs,*yu,*ys,*xu2,*xs2,*xwp,*xgp,*xtp;
    __half *tU,*tS,*tG,*tW,*tT,*tU2,*tS2,*tG2,*tW2,*tT2;
    float *blS1,*blS2;
    cudaGetSymbolAddress((void**)&cnt,  g_cnt);
    cudaGetSymbolAddress((void**)&off,  g_off);
    cudaGetSymbolAddress((void**)&csum, g_csum);
    cudaGetSymbolAddress((void**)&csr,  g_csr);
    cudaGetSymbolAddress((void**)&agg,  g_agg);
    cudaGetSymbolAddress((void**)&xs,   g_xs);
    cudaGetSymbolAddress((void**)&yu,   g_yu);
    cudaGetSymbolAddress((void**)&ys,   g_ys);
    cudaGetSymbolAddress((void**)&xu2,  g_xu2);
    cudaGetSymbolAddress((void**)&xs2,  g_xs2);
    cudaGetSymbolAddress((void**)&tU,   g_tU);
    cudaGetSymbolAddress((void**)&tS,   g_tS);
    cudaGetSymbolAddress((void**)&tG,   g_tG);
    cudaGetSymbolAddress((void**)&tW,   g_tW);
    cudaGetSymbolAddress((void**)&tT,   g_tT);
    cudaGetSymbolAddress((void**)&tU2,  g_tU2);
    cudaGetSymbolAddress((void**)&tS2,  g_tS2);
    cudaGetSymbolAddress((void**)&tG2,  g_tG2);
    cudaGetSymbolAddress((void**)&tW2,  g_tW2);
    cudaGetSymbolAddress((void**)&tT2,  g_tT2);
    cudaGetSymbolAddress((void**)&xwp,  g_xwp);
    cudaGetSymbolAddress((void**)&xgp,  g_xgp);
    cudaGetSymbolAddress((void**)&xtp,  g_xtp);
    cudaGetSymbolAddress((void**)&blS1, g_blS1);
    cudaGetSymbolAddress((void**)&blS2, g_blS2);

    int* cur = cnt + CNT_TOT;
    const int W44 = CC*CC;

    // ---- init ----
    cudaMemsetAsync(cnt, 0, (CNT_TOT + N_SCAN) * sizeof(int));
    cudaMemsetAsync(agg, 0, AGG_TOT * sizeof(float));

    // ---- launch 1: small duals (float W) + weight preconversion + degree count ----
    {
        DualJob jw = { w_emb, Wl1 + 4*W44, tW, Wr1 + 5*W44, bl1 + 5*CC, xwp, NW, 0 };
        DualJob jg = { g_emb, Wl1 + 2*W44, tG, Wr1 + 3*W44, bl1 + 3*CC, xgp, NG, 0 };
        DualJob jt = { t_emb, Wl1 + 6*W44, tT, Wr1 + 7*W44, bl1 + 7*CC, xtp, NT, 0 };
        prep_deg_duals<<<PD_TOT, 256>>>(jw, jg, jt, Wu, Wsw, Wl1, bl1, Wr1, Wl2, bl2, Wr2,
                                        e_u2s, e_g2s, e_w2s, e_t2s, cnt);
    }

    // ---- scans ----
    scan1<<<NCHUNK, 256>>>(cnt, csum);
    scan23<<<NCHUNK, 256>>>(cnt, csum, off);

    // ---- p0: big transforms (occ-3, double-buffered preconverted W) + chains + fill_csr ----
    {
        P0Job ju = { reviews,  PRE_WU,  bu, nullptr,
                     PREK(9),  bl1 + 1*CC, yu,      // yu_pre = xu@Wr1_1 + bl1_1
                     PREK(0),  tU, NU };            // tU = xu@Wl1_0
        P0Job js = { overview, PRE_WSW, bs, xs,
                     PREK(32), blS1, ys,            // ys_pre = xs@WrS1 + blS1
                     PREK(1),  tS, NS };            // tS = xs@Wl1_1
        p0_mega<<<P0_TOT, 256>>>(ju, js, e_u2s, e_g2s, e_w2s, e_t2s, off, cur, csr);
    }

    // ---- gather 1 + s->g/w/t scatter (fused) ----
    {
        ScatJob s0 = { xs, e_g2s + E_GS, e_g2s, agg + AGG_G };
        ScatJob s1 = { xs, e_w2s + E_WS, e_w2s, agg + AGG_W };
        ScatJob s2 = { xs, e_t2s + E_TS, e_t2s, agg + AGG_T };
        gather_scatter<<<GATH_BLK + SCAT_BLK, 256>>>(tU, tS, tG, tW, tT, ys, yu,
                                                     off, csr, s0, s1, s2);
    }

    // ---- wave2 ----
    {
        DualJobP d0 = { yu, PREK(16), tU2, PREK(25), bl2 + 1*CC, xu2, NU, 1 };
        DualJobP d1 = { ys, PREK(17), tS2, PREK(33), blS2,       xs2, NS, 1 };
        FBJobP f0 = { agg + AGG_W, PREK(5), xwp, cnt + CNT_W, PREK(20), tW2, NW };
        FBJobP f1 = { agg + AGG_G, PREK(3), xgp, cnt + CNT_G, PREK(18), tG2, NG };
        FBJobP f2 = { agg + AGG_T, PREK(7), xtp, cnt + CNT_T, PREK(22), tT2, NT };
        wave2<<<W2_TOT, 256>>>(d0, d1, f0, f1, f2);
    }

    // ---- gather 2 ----
    {
        ScatJob sd = { nullptr, nullptr, nullptr, nullptr };
        gather_scatter<<<GATH_BLK, 256>>>(tU2, tS2, tG2, tW2, tT2, xs2, xu2,
                                          off, csr, sd, sd, sd);
    }

    // ---- classifier ----
    dot_score<<<E_LI*16/256, 256>>>(xu2, xs2, eli, eli + E_LI, out, E_LI);
}

// round 17
// speedup vs baseline: 1.0746x; 1.0297x over previous
#include <cuda_runtime.h>
#include <cuda_bf16.h>
#include <cuda_fp16.h>
#include <cstdint>

#define NU 100000
#define NS 50000
#define NG 50
#define NW 20000
#define NT 10
#define CC 64
#define FF 384
#define E_US 1000000
#define E_GS 150000
#define E_WS 50000
#define E_TS 50000
#define E_LI 200000

#define CNT_U   0
#define CNT_SU  (NU)
#define CNT_SG  (NU+NS)
#define CNT_SW  (NU+2*NS)
#define CNT_ST  (NU+3*NS)
#define CNT_G   (NU+4*NS)
#define CNT_W   (NU+4*NS+NG)
#define CNT_T   (NU+4*NS+NG+NW)
#define CNT_TOT (NU+4*NS+NG+NW+NT)

#define N_SCAN  (NU + 4*NS)
#define CSR_TOT (2*E_US + E_GS + E_WS + E_TS)
#define CHUNK   1024
#define NCHUNK  ((N_SCAN + CHUNK - 1) / CHUNK)

#define AGG_G 0
#define AGG_W ((size_t)NG*CC)
#define AGG_T ((size_t)(NG+NW)*CC)
#define AGG_TOT ((size_t)(NG+NW+NT)*CC)

#define U_BLK 782
#define S_BLK 391
#define W_BLK 157

// ---- preconverted K=64 weight store (bf16 hi/lo pairs, [64][32] u32 per matrix) ----
#define PREK(i) (24576 + (i)*2048)
// Wl1_i -> PREK(i), Wr1_i -> PREK(8+i), Wl2_i -> PREK(16+i), Wr2_i -> PREK(24+i),
// WrS1 -> PREK(32), WrS2 -> PREK(33)
#define PRE_SZ  (24576 + 34*2048)
// fragment-major uint4 store for the two K=384 matrices (Wu at 0, Wsw at 6144)
#define WFRAG_SZ (2*6144)

// ---------------- scratch ----------------
__device__ int   g_cnt[CNT_TOT + N_SCAN];
__device__ int   g_off[N_SCAN + 1];
__device__ int   g_csum[NCHUNK];
__device__ int   g_csr[CSR_TOT];
__device__ float g_agg[AGG_TOT];
__device__ uint32_t g_whi[PRE_SZ], g_wlo[PRE_SZ];
__device__ uint4 g_wfrag[WFRAG_SZ];

__device__ float g_xs[NS*CC];
__device__ float g_yu[NU*CC], g_ys[NS*CC];
__device__ float g_xu2[NU*CC], g_xs2[NS*CC];
__device__ __half g_tU[NU*CC], g_tS[NS*CC], g_tG[NG*CC], g_tW[NW*CC], g_tT[NT*CC];
__device__ __half g_tU2[NU*CC], g_tS2[NS*CC], g_tG2[NG*CC], g_tW2[NW*CC], g_tT2[NT*CC];
__device__ float g_xwp[NW*CC], g_xgp[NG*CC], g_xtp[NT*CC];
__device__ float g_blS1[CC], g_blS2[CC];

// ---------------- bf16 split helpers ----------------
__device__ __forceinline__ void split2(float x, float y, uint32_t& hi, uint32_t& lo) {
    __nv_bfloat162 h = __floats2bfloat162_rn(x, y);
    float2 hf = __bfloat1622float2(h);
    __nv_bfloat162 l = __floats2bfloat162_rn(x - hf.x, y - hf.y);
    hi = *(uint32_t*)&h;
    lo = *(uint32_t*)&l;
}
__device__ __forceinline__ void mma16(float* d, const uint32_t* a, uint32_t b0, uint32_t b1) {
    asm("mma.sync.aligned.m16n8k16.row.col.f32.bf16.bf16.f32 "
        "{%0,%1,%2,%3}, {%4,%5,%6,%7}, {%8,%9}, {%0,%1,%2,%3};"
        : "+f"(d[0]), "+f"(d[1]), "+f"(d[2]), "+f"(d[3])
        : "r"(a[0]), "r"(a[1]), "r"(a[2]), "r"(a[3]), "r"(b0), "r"(b1));
}

// float staging (launch-1 duals only)
__device__ __forceinline__ void stage_w(const float* W, int ld, int k0,
                                        uint32_t (*Whi)[36], uint32_t (*Wlo)[36], int tid) {
#pragma unroll
    for (int i = tid; i < 64 * 32; i += 256) {
        int n = i >> 5, kp = i & 31;
        float2 w = *(const float2*)(W + (size_t)n * ld + k0 + 2 * kp);
        split2(w.x, w.y, Whi[n][kp], Wlo[n][kp]);
    }
}

// preconverted staging: plain copies (K=64 matrices)
__device__ __forceinline__ void stage_pre(int woff,
                                          uint32_t (*Whi)[36], uint32_t (*Wlo)[36], int tid) {
    const uint32_t* hi = g_whi + woff;
    const uint32_t* lo = g_wlo + woff;
#pragma unroll
    for (int i = tid; i < 64 * 32; i += 256) {
        int n = i >> 5, kp = i & 31;
        Whi[n][kp] = hi[n * 32 + kp];
        Wlo[n][kp] = lo[n * 32 + kp];
    }
}

__device__ __forceinline__ void mma_shared(float (*acc)[4], const uint32_t* ah, const uint32_t* al,
                                           const uint32_t (*Whi)[36], const uint32_t (*Wlo)[36],
                                           int ks, int g, int tg) {
#pragma unroll
    for (int j = 0; j < 8; j++) {
        uint32_t bh0 = Whi[j*8+g][ks*8+tg], bh1 = Whi[j*8+g][ks*8+tg+4];
        uint32_t bl0 = Wlo[j*8+g][ks*8+tg], bl1 = Wlo[j*8+g][ks*8+tg+4];
        mma16(acc[j], ah, bh0, bh1);
        mma16(acc[j], al, bh0, bh1);
        mma16(acc[j], ah, bl0, bl1);
    }
}

__device__ __forceinline__ void load_afrag(const float* A0, const float* A1, int kk, int relu,
                                           uint32_t* ah, uint32_t* al) {
    float2 a00 = *(const float2*)(A0 + kk);
    float2 a10 = *(const float2*)(A1 + kk);
    float2 a01 = *(const float2*)(A0 + kk + 8);
    float2 a11 = *(const float2*)(A1 + kk + 8);
    if (relu) {
        a00.x=fmaxf(a00.x,0.f); a00.y=fmaxf(a00.y,0.f);
        a10.x=fmaxf(a10.x,0.f); a10.y=fmaxf(a10.y,0.f);
        a01.x=fmaxf(a01.x,0.f); a01.y=fmaxf(a01.y,0.f);
        a11.x=fmaxf(a11.x,0.f); a11.y=fmaxf(a11.y,0.f);
    }
    split2(a00.x, a00.y, ah[0], al[0]);
    split2(a10.x, a10.y, ah[1], al[1]);
    split2(a01.x, a01.y, ah[2], al[2]);
    split2(a11.x, a11.y, ah[3], al[3]);
}

// register-chained GEMM using preconverted K=64 weights (L1-resident)
__device__ __forceinline__ void chain_pre(const float (*e)[4], int woff,
                                          float (*a2)[4], int g, int tg) {
    const uint32_t* whi = g_whi + woff;
    const uint32_t* wlo = g_wlo + woff;
#pragma unroll
    for (int jj = 0; jj < 4; jj++) {
        uint32_t ah[4], al[4];
        split2(e[2*jj][0],   e[2*jj][1],   ah[0], al[0]);
        split2(e[2*jj][2],   e[2*jj][3],   ah[1], al[1]);
        split2(e[2*jj+1][0], e[2*jj+1][1], ah[2], al[2]);
        split2(e[2*jj+1][2], e[2*jj+1][3], ah[3], al[3]);
#pragma unroll
        for (int j = 0; j < 8; j++) {
            int r = (j*8+g)*32 + 8*jj + tg;
            uint32_t bh0 = whi[r], bh1 = whi[r+4];
            uint32_t bl0 = wlo[r], bl1 = wlo[r+4];
            mma16(a2[j], ah, bh0, bh1);
            mma16(a2[j], al, bh0, bh1);
            mma16(a2[j], ah, bl0, bl1);
        }
    }
}

__device__ __forceinline__ void store_frag(const float (*acc)[4], const float* bias,
                                           float* out, int mr0, int M, int tg) {
#pragma unroll
    for (int j = 0; j < 8; j++) {
        int n = j*8 + 2*tg;
        float b0 = bias ? bias[n] : 0.f, b1 = bias ? bias[n+1] : 0.f;
        if (mr0 < M)
            *(float2*)(out + (size_t)mr0*CC + n) = make_float2(acc[j][0]+b0, acc[j][1]+b1);
        if (mr0+8 < M)
            *(float2*)(out + (size_t)(mr0+8)*CC + n) = make_float2(acc[j][2]+b0, acc[j][3]+b1);
    }
}

__device__ __forceinline__ void store_frag_h(const float (*acc)[4], __half* out,
                                             int mr0, int M, int tg) {
#pragma unroll
    for (int j = 0; j < 8; j++) {
        int n = j*8 + 2*tg;
        if (mr0 < M)
            *(__half2*)(out + (size_t)mr0*CC + n) = __floats2half2_rn(acc[j][0], acc[j][1]);
        if (mr0+8 < M)
            *(__half2*)(out + (size_t)(mr0+8)*CC + n) = __floats2half2_rn(acc[j][2], acc[j][3]);
    }
}

// ---------------- job structs ----------------
struct DualJob {
    const float* A; const float* W0; __half* o0;
    const float* W1; const float* b1; float* o1; int M; int relu_in;
};
struct DualJobP {
    const float* A; int w0; __half* o0;
    int w1; const float* b1; float* o1; int M; int relu_in;
};
struct FBJobP {
    const float* A; int w1; const float* accin; const int* cnt;
    int wc; __half* out; int M;
};
struct P0Job {
    const float* A; int wfrag; const float* bias; float* xout;
    int wc0; const float* bc0; float* oc0;
    int wc1; __half* oc1;
    int M;
};
struct ScatJob { const float* x; const int* src; const int* dst; float* out; };

// ---------------- GEMM bodies ----------------
__device__ __forceinline__ void dual_body_f(const DualJob& jb, int bx,
                                            uint32_t (*WhiA)[36], uint32_t (*WloA)[36],
                                            uint32_t (*WhiB)[36], uint32_t (*WloB)[36]) {
    const int m0 = bx * 128;
    const int tid = threadIdx.x, wid = tid >> 5, lane = tid & 31;
    const int g = lane >> 2, tg = lane & 3;

    stage_w(jb.W0, CC, 0, WhiA, WloA, tid);
    stage_w(jb.W1, CC, 0, WhiB, WloB, tid);
    __syncthreads();

    float acc[2][8][4];
#pragma unroll
    for (int w = 0; w < 2; w++)
#pragma unroll
        for (int j = 0; j < 8; j++) { acc[w][j][0]=acc[w][j][1]=acc[w][j][2]=acc[w][j][3]=0.f; }

    const int mtop = jb.M - 1;
    const int mr0 = m0 + wid * 16 + g;
    const float* A0 = jb.A + (size_t)min(mr0,     mtop) * CC;
    const float* A1 = jb.A + (size_t)min(mr0 + 8, mtop) * CC;

#pragma unroll
    for (int ks = 0; ks < 4; ks++) {
        uint32_t ah[4], al[4];
        load_afrag(A0, A1, ks*16 + 2*tg, jb.relu_in, ah, al);
        mma_shared(acc[0], ah, al, WhiA, WloA, ks, g, tg);
        mma_shared(acc[1], ah, al, WhiB, WloB, ks, g, tg);
    }
    store_frag_h(acc[0], jb.o0, mr0, jb.M, tg);
    store_frag(acc[1], jb.b1, jb.o1, mr0, jb.M, tg);
}

__device__ __forceinline__ void dual_body_p(const DualJobP& jb, int bx,
                                            uint32_t (*WhiA)[36], uint32_t (*WloA)[36],
                                            uint32_t (*WhiB)[36], uint32_t (*WloB)[36]) {
    const int m0 = bx * 128;
    const int tid = threadIdx.x, wid = tid >> 5, lane = tid & 31;
    const int g = lane >> 2, tg = lane & 3;

    stage_pre(jb.w0, WhiA, WloA, tid);
    stage_pre(jb.w1, WhiB, WloB, tid);
    __syncthreads();

    float acc[2][8][4];
#pragma unroll
    for (int w = 0; w < 2; w++)
#pragma unroll
        for (int j = 0; j < 8; j++) { acc[w][j][0]=acc[w][j][1]=acc[w][j][2]=acc[w][j][3]=0.f; }

    const int mtop = jb.M - 1;
    const int mr0 = m0 + wid * 16 + g;
    const float* A0 = jb.A + (size_t)min(mr0,     mtop) * CC;
    const float* A1 = jb.A + (size_t)min(mr0 + 8, mtop) * CC;

#pragma unroll
    for (int ks = 0; ks < 4; ks++) {
        uint32_t ah[4], al[4];
        load_afrag(A0, A1, ks*16 + 2*tg, jb.relu_in, ah, al);
        mma_shared(acc[0], ah, al, WhiA, WloA, ks, g, tg);
        mma_shared(acc[1], ah, al, WhiB, WloB, ks, g, tg);
    }
    store_frag_h(acc[0], jb.o0, mr0, jb.M, tg);
    store_frag(acc[1], jb.b1, jb.o1, mr0, jb.M, tg);
}

__device__ __forceinline__ void fb_body_p(const FBJobP& jb, int bx,
                                          uint32_t (*Whi)[36], uint32_t (*Wlo)[36]) {
    const int m0 = bx * 128;
    const int tid = threadIdx.x, wid = tid >> 5, lane = tid & 31;
    const int g = lane >> 2, tg = lane & 3;

    stage_pre(jb.w1, Whi, Wlo, tid);
    __syncthreads();

    float acc1[8][4];
#pragma unroll
    for (int j = 0; j < 8; j++) { acc1[j][0]=acc1[j][1]=acc1[j][2]=acc1[j][3]=0.f; }

    const int mtop = jb.M - 1;
    const int mr0 = m0 + wid * 16 + g;
    const int r0 = min(mr0, mtop), r1 = min(mr0 + 8, mtop);
    const float* A0 = jb.A + (size_t)r0 * CC;
    const float* A1 = jb.A + (size_t)r1 * CC;

#pragma unroll
    for (int ks = 0; ks < 4; ks++) {
        uint32_t ah[4], al[4];
        load_afrag(A0, A1, ks*16 + 2*tg, 0, ah, al);
        mma_shared(acc1, ah, al, Whi, Wlo, ks, g, tg);
    }

    const float s0 = 1.f / fmaxf((float)jb.cnt[r0], 1.f);
    const float s1 = 1.f / fmaxf((float)jb.cnt[r1], 1.f);
#pragma unroll
    for (int j = 0; j < 8; j++) {
        int n = j*8 + 2*tg;
        float2 c0 = *(const float2*)(jb.accin + (size_t)r0 * CC + n);
        float2 c1 = *(const float2*)(jb.accin + (size_t)r1 * CC + n);
        acc1[j][0] = fmaxf(acc1[j][0]*s0 + c0.x, 0.f);
        acc1[j][1] = fmaxf(acc1[j][1]*s0 + c0.y, 0.f);
        acc1[j][2] = fmaxf(acc1[j][2]*s1 + c1.x, 0.f);
        acc1[j][3] = fmaxf(acc1[j][3]*s1 + c1.y, 0.f);
    }

    float a2[8][4];
#pragma unroll
    for (int j = 0; j < 8; j++) { a2[j][0]=a2[j][1]=a2[j][2]=a2[j][3]=0.f; }
    chain_pre(acc1, jb.wc, a2, g, tg);
    store_frag_h(a2, jb.out, mr0, jb.M, tg);
}

// ---------------- launch 1: small duals + weight preconvert + deg count ----
#define PD_PREP (W_BLK + 2)
#define PD_CONV (PD_PREP + 16)
#define PD_NCONV 64
#define PD_DEG  (PD_CONV + PD_NCONV)
#define PD_DEGBLK 512
#define PD_TOT  (PD_DEG + PD_DEGBLK)
#define CONV_K64 65536
#define CONV_TOT (CONV_K64 + WFRAG_SZ)

__global__ void __launch_bounds__(256) prep_deg_duals(
    const DualJob jw, const DualJob jg, const DualJob jt,
    const float* __restrict__ Wu, const float* __restrict__ Wsw,
    const float* __restrict__ Wl1, const float* __restrict__ bl1,
    const float* __restrict__ Wr1,
    const float* __restrict__ Wl2, const float* __restrict__ bl2,
    const float* __restrict__ Wr2,
    const int* __restrict__ u2s, const int* __restrict__ g2s,
    const int* __restrict__ w2s, const int* __restrict__ t2s,
    int* __restrict__ cnt)
{
    __shared__ uint32_t Whi[2][64][36], Wlo[2][64][36];
    int bx = blockIdx.x;
    if (bx < W_BLK)     { dual_body_f(jw, bx, Whi[0], Wlo[0], Whi[1], Wlo[1]); return; }
    if (bx == W_BLK)    { dual_body_f(jg, 0,  Whi[0], Wlo[0], Whi[1], Wlo[1]); return; }
    if (bx == W_BLK+1)  { dual_body_f(jt, 0,  Whi[0], Wlo[0], Whi[1], Wlo[1]); return; }
    if (bx < PD_CONV) {
        int i = (bx - PD_PREP) * 256 + threadIdx.x;
        if (i < 2048) {
            float x1=0.f,y1=0.f,x2=0.f,y2=0.f;
#pragma unroll
            for (int m = 0; m < 4; m++) {
                const float* w1 = Wr1 + (size_t)(2*m)*4096;
                const float* w2 = Wr2 + (size_t)(2*m)*4096;
                x1 += w1[2*i]; y1 += w1[2*i+1];
                x2 += w2[2*i]; y2 += w2[2*i+1];
            }
            split2(x1, y1, g_whi[PREK(32)+i], g_wlo[PREK(32)+i]);
            split2(x2, y2, g_whi[PREK(33)+i], g_wlo[PREK(33)+i]);
        }
        if (i < CC) {
            g_blS1[i] = bl1[i] + bl1[2*CC+i] + bl1[4*CC+i] + bl1[6*CC+i];
            g_blS2[i] = bl2[i] + bl2[2*CC+i] + bl2[4*CC+i] + bl2[6*CC+i];
        }
        return;
    }
    if (bx < PD_DEG) {
        const float* srcs[4] = { Wl1, Wr1, Wl2, Wr2 };
        const int stride = PD_NCONV * 256;
        for (int i = (bx - PD_CONV) * 256 + threadIdx.x; i < CONV_TOT; i += stride) {
            if (i < CONV_K64) {
                int t = i >> 14;                // /16384
                int local = i & 16383;
                float2 w = *(const float2*)(srcs[t] + 2*(size_t)local);
                split2(w.x, w.y, g_whi[24576 + t*16384 + local], g_wlo[24576 + t*16384 + local]);
            } else {
                int j2 = i - CONV_K64;
                int mat = j2 / 6144;
                int r = j2 - mat*6144;
                int n = r / 96, rem = r - n*96;
                int ksg = rem >> 2, tg = rem & 3;
                const float* base = (mat ? Wsw : Wu) + (size_t)n*FF + ksg*16 + 2*tg;
                uint32_t h0,l0,h1,l1;
                split2(base[0], base[1], h0, l0);
                split2(base[8], base[9], h1, l1);
                g_wfrag[j2] = make_uint4(h0, h1, l0, l1);
            }
        }
        return;
    }
    const int stride = PD_DEGBLK * 256;
    int base = (bx - PD_DEG) * 256 + threadIdx.x;
    for (int i = base; i < E_US; i += stride) {
        atomicAdd(cnt + CNT_U  + u2s[i], 1);
        atomicAdd(cnt + CNT_SU + u2s[E_US + i], 1);
    }
    for (int i = base; i < E_GS; i += stride) {
        atomicAdd(cnt + CNT_G  + g2s[i], 1);
        atomicAdd(cnt + CNT_SG + g2s[E_GS + i], 1);
    }
    for (int i = base; i < E_WS; i += stride) {
        atomicAdd(cnt + CNT_W  + w2s[i], 1);
        atomicAdd(cnt + CNT_SW + w2s[E_WS + i], 1);
    }
    for (int i = base; i < E_TS; i += stride) {
        atomicAdd(cnt + CNT_T  + t2s[i], 1);
        atomicAdd(cnt + CNT_ST + t2s[E_TS + i], 1);
    }
}

// ---------------- scans ----------------
__global__ void scan1(const int* __restrict__ cnt, int* __restrict__ csum) {
    __shared__ int sh[8];
    int c = blockIdx.x, t = threadIdx.x, base = c * CHUNK;
    int s = 0;
#pragma unroll
    for (int q = 0; q < 4; q++) {
        int idx = base + t*4 + q;
        if (idx < N_SCAN) s += cnt[idx];
    }
    for (int o = 16; o; o >>= 1) s += __shfl_down_sync(~0u, s, o);
    if ((t & 31) == 0) sh[t >> 5] = s;
    __syncthreads();
    if (t == 0) { int tot = 0; for (int w = 0; w < 8; w++) tot += sh[w]; csum[c] = tot; }
}

__global__ void scan23(const int* __restrict__ cnt, const int* __restrict__ csum,
                       int* __restrict__ off) {
    __shared__ int sh[8], sh2[8], basev;
    int c = blockIdx.x, t = threadIdx.x;
    int lane = t & 31, w = t >> 5;

    int p = 0;
    for (int i = t; i < c; i += 256) p += csum[i];
    for (int o = 16; o; o >>= 1) p += __shfl_down_sync(~0u, p, o);
    if (lane == 0) sh2[w] = p;
    __syncthreads();
    if (t == 0) { int a = 0; for (int i = 0; i < 8; i++) a += sh2[i]; basev = a; }
    __syncthreads();
    const int cbase = basev;

    int base = c * CHUNK;
    int v[4]; int s = 0;
#pragma unroll
    for (int q = 0; q < 4; q++) {
        int idx = base + t*4 + q;
        v[q] = (idx < N_SCAN) ? cnt[idx] : 0;
        s += v[q];
    }
    int incl = s;
    for (int o = 1; o < 32; o <<= 1) {
        int x = __shfl_up_sync(~0u, incl, o);
        if (lane >= o) incl += x;
    }
    if (lane == 31) sh[w] = incl;
    __syncthreads();
    if (t == 0) { int a = 0; for (int i = 0; i < 8; i++) { int x = sh[i]; sh[i] = a; a += x; } }
    __syncthreads();
    int excl = incl - s + sh[w] + cbase;
#pragma unroll
    for (int q = 0; q < 4; q++) {
        int idx = base + t*4 + q;
        if (idx < N_SCAN) off[idx] = excl;
        excl += v[q];
        if (idx == N_SCAN - 1) off[N_SCAN] = excl;
    }
}

// ---------------- p0 mega: cp.async A pipeline + direct-L1 W fragments ----------------
#define P0_JU   U_BLK
#define P0_FILL (U_BLK + S_BLK)
#define P0_FILLBLK 3907
#define P0_TOT  (P0_FILL + P0_FILLBLK)
#define NCHK 12

__global__ void __launch_bounds__(256, 3) p0_mega(
    const P0Job j0, const P0Job j1,
    const int* __restrict__ u2s, const int* __restrict__ g2s,
    const int* __restrict__ w2s, const int* __restrict__ t2s,
    const int* __restrict__ off, int* __restrict__ cur, int* __restrict__ csr)
{
    __shared__ float Ash[2][128][36];
    int bx = blockIdx.x;
    if (bx >= P0_FILL) {
        int i = (bx - P0_FILL) * 256 + threadIdx.x;
        if (i < E_US) {
            int u = u2s[i], s = u2s[E_US + i];
            int n0 = CNT_SU + s;
            csr[off[n0] + atomicAdd(cur + n0, 1)] = u;
            int n1 = CNT_U + u;
            csr[off[n1] + atomicAdd(cur + n1, 1)] = s;
        }
        if (i < E_GS) {
            int gg = g2s[i], s = g2s[E_GS + i];
            int n = CNT_SG + s;
            csr[off[n] + atomicAdd(cur + n, 1)] = gg;
        }
        if (i < E_WS) {
            int ww = w2s[i], s = w2s[E_WS + i];
            int n = CNT_SW + s;
            csr[off[n] + atomicAdd(cur + n, 1)] = ww;
        }
        if (i < E_TS) {
            int tt = t2s[i], s = t2s[E_TS + i];
            int n = CNT_ST + s;
            csr[off[n] + atomicAdd(cur + n, 1)] = tt;
        }
        return;
    }
    const P0Job jb = (bx >= P0_JU) ? j1 : j0;
    const int m0 = ((bx >= P0_JU) ? bx - P0_JU : bx) * 128;

    const int tid = threadIdx.x, wid = tid >> 5, lane = tid & 31;
    const int g = lane >> 2, tg = lane & 3;
    const int mtop = jb.M - 1;

    uint32_t ash = (uint32_t)__cvta_generic_to_shared(&Ash[0][0][0]);
    // per-thread fixed staging slots: 4 x 16B per chunk
    int r0s = (0*256 + tid) >> 3, s0s = (0*256 + tid) & 7;
    int r1s = (1*256 + tid) >> 3, s1s = (1*256 + tid) & 7;
    int r2s = (2*256 + tid) >> 3, s2s = (2*256 + tid) & 7;
    int r3s = (3*256 + tid) >> 3, s3s = (3*256 + tid) & 7;
    const float* a0p = jb.A + (size_t)min(m0 + r0s, mtop) * FF + s0s*4;
    const float* a1p = jb.A + (size_t)min(m0 + r1s, mtop) * FF + s1s*4;
    const float* a2p = jb.A + (size_t)min(m0 + r2s, mtop) * FF + s2s*4;
    const float* a3p = jb.A + (size_t)min(m0 + r3s, mtop) * FF + s3s*4;
    uint32_t d0 = ash + (uint32_t)(r0s*36 + s0s*4)*4u;
    uint32_t d1 = ash + (uint32_t)(r1s*36 + s1s*4)*4u;
    uint32_t d2 = ash + (uint32_t)(r2s*36 + s2s*4)*4u;
    uint32_t d3 = ash + (uint32_t)(r3s*36 + s3s*4)*4u;
    const uint32_t bufB = 128*36*4u;

#define P0_ISSUE(c, buf) do {                                                        \
    uint32_t bo = (buf) ? bufB : 0u;                                                 \
    int co = (c) * 32;                                                               \
    asm volatile("cp.async.cg.shared.global [%0], [%1], 16;" :: "r"(d0+bo), "l"(a0p+co)); \
    asm volatile("cp.async.cg.shared.global [%0], [%1], 16;" :: "r"(d1+bo), "l"(a1p+co)); \
    asm volatile("cp.async.cg.shared.global [%0], [%1], 16;" :: "r"(d2+bo), "l"(a2p+co)); \
    asm volatile("cp.async.cg.shared.global [%0], [%1], 16;" :: "r"(d3+bo), "l"(a3p+co)); \
    asm volatile("cp.async.commit_group;"); } while (0)

    P0_ISSUE(0, 0);
    P0_ISSUE(1, 1);

    float acc1[8][4];
#pragma unroll
    for (int j = 0; j < 8; j++) { acc1[j][0]=acc1[j][1]=acc1[j][2]=acc1[j][3]=0.f; }

    const int Rl0 = wid*16 + g, Rl1 = Rl0 + 8;

#pragma unroll
    for (int c = 0; c < NCHK; c++) {
        if (c < NCHK-1) asm volatile("cp.async.wait_group 1;");
        else            asm volatile("cp.async.wait_group 0;");
        __syncthreads();
        const float* Ab = &Ash[c & 1][0][0];
#pragma unroll
        for (int ks2 = 0; ks2 < 2; ks2++) {
            const int ksg = c*2 + ks2;
            const int cl = ks2*16 + 2*tg;
            float2 a00 = *(const float2*)(Ab + Rl0*36 + cl);
            float2 a10 = *(const float2*)(Ab + Rl1*36 + cl);
            float2 a01 = *(const float2*)(Ab + Rl0*36 + cl + 8);
            float2 a11 = *(const float2*)(Ab + Rl1*36 + cl + 8);
            uint32_t ah[4], al[4];
            split2(a00.x, a00.y, ah[0], al[0]);
            split2(a10.x, a10.y, ah[1], al[1]);
            split2(a01.x, a01.y, ah[2], al[2]);
            split2(a11.x, a11.y, ah[3], al[3]);
#pragma unroll
            for (int j = 0; j < 8; j++) {
                uint4 wf = g_wfrag[jb.wfrag + (((j*8+g)*24 + ksg)*4 + tg)];
                mma16(acc1[j], ah, wf.x, wf.y);
                mma16(acc1[j], al, wf.x, wf.y);
                mma16(acc1[j], ah, wf.z, wf.w);
            }
        }
        __syncthreads();
        if (c + 2 < NCHK) P0_ISSUE(c + 2, c & 1);
    }

    const int mr0 = m0 + wid*16 + g;
    // bias -> acc1 is the transformed feature x
#pragma unroll
    for (int j = 0; j < 8; j++) {
        int n = j*8 + 2*tg;
        float b0 = jb.bias[n], b1 = jb.bias[n+1];
        acc1[j][0] += b0; acc1[j][1] += b1;
        acc1[j][2] += b0; acc1[j][3] += b1;
    }
    if (jb.xout) store_frag(acc1, nullptr, jb.xout, mr0, jb.M, tg);

    float a2[8][4];
#pragma unroll
    for (int j = 0; j < 8; j++) { a2[j][0]=a2[j][1]=a2[j][2]=a2[j][3]=0.f; }
    chain_pre(acc1, jb.wc0, a2, g, tg);
    store_frag(a2, jb.bc0, jb.oc0, mr0, jb.M, tg);

#pragma unroll
    for (int j = 0; j < 8; j++) { a2[j][0]=a2[j][1]=a2[j][2]=a2[j][3]=0.f; }
    chain_pre(acc1, jb.wc1, a2, g, tg);
    store_frag_h(a2, jb.oc1, mr0, jb.M, tg);
#undef P0_ISSUE
}

// ---------------- gather (+optional fused scatter blocks) ----------------
#define GATH_BLK 18750
#define SCAT_E   (E_GS + E_WS + E_TS)
#define SCAT_BLK ((SCAT_E * 8 + 255) / 256)

__global__ void __launch_bounds__(256) gather_scatter(
    const __half* __restrict__ tU, const __half* __restrict__ tS,
    const __half* __restrict__ tG, const __half* __restrict__ tW, const __half* __restrict__ tT,
    float* __restrict__ outS, float* __restrict__ outU,
    const int* __restrict__ off, const int* __restrict__ csr,
    const ScatJob s0, const ScatJob s1, const ScatJob s2)
{
    int bx = blockIdx.x;
    if (bx >= GATH_BLK) {
        int gid = (bx - GATH_BLK) * 256 + threadIdx.x;
        int ge = gid >> 3;
        if (ge >= SCAT_E) return;
        int part = gid & 7;
        const ScatJob jb = (ge < E_GS) ? s0 : (ge < E_GS + E_WS ? s1 : s2);
        int e = (ge < E_GS) ? ge : (ge < E_GS + E_WS ? ge - E_GS : ge - E_GS - E_WS);
        int s = jb.src[e], d = jb.dst[e];
        const float4* xp = (const float4*)(jb.x + (size_t)s * CC);
        float4*       op = (float4*)(jb.out + (size_t)d * CC);
        atomicAdd(op + part,     xp[part]);
        atomicAdd(op + part + 8, xp[part + 8]);
        return;
    }
    int gw = (bx * 256 + threadIdx.x) >> 5;
    int lane = threadIdx.x & 31;
    int hf = lane >> 4;
    int col = (lane & 15) * 4;
    float4 s = make_float4(0.f, 0.f, 0.f, 0.f);
    float* o;

    if (gw < NS) {
        const int d = gw;
        const int node[4] = { CNT_SU + d, CNT_SG + d, CNT_SW + d, CNT_ST + d };
        const __half* buf[4] = { tU, tG, tW, tT };
#pragma unroll
        for (int f = 0; f < 4; f++) {
            int b = off[node[f]], e = off[node[f] + 1];
            float4 fa = make_float4(0.f, 0.f, 0.f, 0.f);
#pragma unroll 2
            for (int i = b + hf; i < e; i += 2) {
                int src = csr[i];
                uint2 raw = *(const uint2*)(buf[f] + (size_t)src * CC + col);
                float2 v0 = __half22float2(*(__half2*)&raw.x);
                float2 v1 = __half22float2(*(__half2*)&raw.y);
                fa.x += v0.x; fa.y += v0.y; fa.z += v1.x; fa.w += v1.y;
            }
            float inv = 1.f / fmaxf((float)(e - b), 1.f);
            s.x += fa.x * inv; s.y += fa.y * inv; s.z += fa.z * inv; s.w += fa.w * inv;
        }
        o = outS + (size_t)d * CC + col;
    } else if (gw < NS + NU) {
        const int d = gw - NS;
        int b = off[CNT_U + d], e = off[CNT_U + d + 1];
        float4 fa = make_float4(0.f, 0.f, 0.f, 0.f);
#pragma unroll 2
        for (int i = b + hf; i < e; i += 2) {
            int src = csr[i];
            uint2 raw = *(const uint2*)(tS + (size_t)src * CC + col);
            float2 v0 = __half22float2(*(__half2*)&raw.x);
            float2 v1 = __half22float2(*(__half2*)&raw.y);
            fa.x += v0.x; fa.y += v0.y; fa.z += v1.x; fa.w += v1.y;
        }
        float inv = 1.f / fmaxf((float)(e - b), 1.f);
        s.x = fa.x * inv; s.y = fa.y * inv; s.z = fa.z * inv; s.w = fa.w * inv;
        o = outU + (size_t)d * CC + col;
    } else return;

    s.x += __shfl_xor_sync(~0u, s.x, 16);
    s.y += __shfl_xor_sync(~0u, s.y, 16);
    s.z += __shfl_xor_sync(~0u, s.z, 16);
    s.w += __shfl_xor_sync(~0u, s.w, 16);
    if (hf == 0) {
        float4 c = *(const float4*)o;
        *(float4*)o = make_float4(c.x + s.x, c.y + s.y, c.z + s.z, c.w + s.w);
    }
}

// ---------------- wave2 ----------------
#define W2_B1 (U_BLK)
#define W2_B2 (U_BLK + S_BLK)
#define W2_B3 (U_BLK + S_BLK + W_BLK)
#define W2_TOT (U_BLK + S_BLK + W_BLK + 2)

__global__ void __launch_bounds__(256) wave2(
    const DualJobP d0, const DualJobP d1,
    const FBJobP f0, const FBJobP f1, const FBJobP f2)
{
    __shared__ uint32_t Whi[2][64][36], Wlo[2][64][36];
    int bx = blockIdx.x;
    if (bx < W2_B1)      { dual_body_p(d0, bx,          Whi[0], Wlo[0], Whi[1], Wlo[1]); return; }
    if (bx < W2_B2)      { dual_body_p(d1, bx - W2_B1,  Whi[0], Wlo[0], Whi[1], Wlo[1]); return; }
    if (bx < W2_B3)      { fb_body_p(f0, bx - W2_B2,    Whi[0], Wlo[0]); return; }
    if (bx == W2_B3)     { fb_body_p(f1, 0,             Whi[0], Wlo[0]); return; }
    fb_body_p(f2, 0, Whi[0], Wlo[0]);
}

// ---------------- classifier ----------------
__global__ void dot_score(const float* __restrict__ xu, const float* __restrict__ xs,
                          const int* __restrict__ ui, const int* __restrict__ si,
                          float* __restrict__ out, int E) {
    int gid = blockIdx.x * blockDim.x + threadIdx.x;
    int e = gid >> 4;
    int j = (gid & 15) << 2;
    int ec = (e < E) ? e : (E - 1);
    float4 a = *(const float4*)(xu + (size_t)ui[ec] * CC + j);
    float4 b = *(const float4*)(xs + (size_t)si[ec] * CC + j);
    float d = a.x*b.x + a.y*b.y + a.z*b.z + a.w*b.w;
    d += __shfl_xor_sync(0xffffffffu, d, 1);
    d += __shfl_xor_sync(0xffffffffu, d, 2);
    d += __shfl_xor_sync(0xffffffffu, d, 4);
    d += __shfl_xor_sync(0xffffffffu, d, 8);
    if ((gid & 15) == 0 && e < E) out[e] = d;
}

static inline int cdiv(int a, int b) { return (a + b - 1) / b; }

extern "C" void kernel_launch(void* const* d_in, const int* in_sizes, int n_in,
                              void* d_out, int out_size)
{
    const float* reviews  = (const float*)d_in[0];
    const float* overview = (const float*)d_in[1];
    const float* g_emb    = (const float*)d_in[2];
    const float* w_emb    = (const float*)d_in[3];
    const float* t_emb    = (const float*)d_in[4];
    const float* Wu  = (const float*)d_in[5];
    const float* bu  = (const float*)d_in[6];
    const float* Wsw = (const float*)d_in[7];
    const float* bs  = (const float*)d_in[8];
    const float* Wl1 = (const float*)d_in[9];
    const float* bl1 = (const float*)d_in[10];
    const float* Wr1 = (const float*)d_in[11];
    const float* Wl2 = (const float*)d_in[12];
    const float* bl2 = (const float*)d_in[13];
    const float* Wr2 = (const float*)d_in[14];
    const int* e_u2s = (const int*)d_in[15];
    const int* e_g2s = (const int*)d_in[16];
    const int* e_w2s = (const int*)d_in[17];
    const int* e_t2s = (const int*)d_in[18];
    const int* eli   = (const int*)d_in[19];
    float* out = (float*)d_out;

    int *cnt,*off,*csum,*csr;
    float *agg,*xs,*yu,*ys,*xu2,*xs2,*xwp,*xgp,*xtp;
    __half *tU,*tS,*tG,*tW,*tT,*tU2,*tS2,*tG2,*tW2,*tT2;
    float *blS1,*blS2;
    cudaGetSymbolAddress((void**)&cnt,  g_cnt);
    cudaGetSymbolAddress((void**)&off,  g_off);
    cudaGetSymbolAddress((void**)&csum, g_csum);
    cudaGetSymbolAddress((void**)&csr,  g_csr);
    cudaGetSymbolAddress((void**)&agg,  g_agg);
    cudaGetSymbolAddress((void**)&xs,   g_xs);
    cudaGetSymbolAddress((void**)&yu,   g_yu);
    cudaGetSymbolAddress((void**)&ys,   g_ys);
    cudaGetSymbolAddress((void**)&xu2,  g_xu2);
    cudaGetSymbolAddress((void**)&xs2,  g_xs2);
    cudaGetSymbolAddress((void**)&tU,   g_tU);
    cudaGetSymbolAddress((void**)&tS,   g_tS);
    cudaGetSymbolAddress((void**)&tG,   g_tG);
    cudaGetSymbolAddress((void**)&tW,   g_tW);
    cudaGetSymbolAddress((void**)&tT,   g_tT);
    cudaGetSymbolAddress((void**)&tU2,  g_tU2);
    cudaGetSymbolAddress((void**)&tS2,  g_tS2);
    cudaGetSymbolAddress((void**)&tG2,  g_tG2);
    cudaGetSymbolAddress((void**)&tW2,  g_tW2);
    cudaGetSymbolAddress((void**)&tT2,  g_tT2);
    cudaGetSymbolAddress((void**)&xwp,  g_xwp);
    cudaGetSymbolAddress((void**)&xgp,  g_xgp);
    cudaGetSymbolAddress((void**)&xtp,  g_xtp);
    cudaGetSymbolAddress((void**)&blS1, g_blS1);
    cudaGetSymbolAddress((void**)&blS2, g_blS2);

    int* cur = cnt + CNT_TOT;
    const int W44 = CC*CC;

    // ---- init ----
    cudaMemsetAsync(cnt, 0, (CNT_TOT + N_SCAN) * sizeof(int));
    cudaMemsetAsync(agg, 0, AGG_TOT * sizeof(float));

    // ---- launch 1: small duals (float W) + weight preconversion + degree count ----
    {
        DualJob jw = { w_emb, Wl1 + 4*W44, tW, Wr1 + 5*W44, bl1 + 5*CC, xwp, NW, 0 };
        DualJob jg = { g_emb, Wl1 + 2*W44, tG, Wr1 + 3*W44, bl1 + 3*CC, xgp, NG, 0 };
        DualJob jt = { t_emb, Wl1 + 6*W44, tT, Wr1 + 7*W44, bl1 + 7*CC, xtp, NT, 0 };
        prep_deg_duals<<<PD_TOT, 256>>>(jw, jg, jt, Wu, Wsw, Wl1, bl1, Wr1, Wl2, bl2, Wr2,
                                        e_u2s, e_g2s, e_w2s, e_t2s, cnt);
    }

    // ---- scans ----
    scan1<<<NCHUNK, 256>>>(cnt, csum);
    scan23<<<NCHUNK, 256>>>(cnt, csum, off);

    // ---- p0: async-streamed big transforms + chains + fill_csr ----
    {
        P0Job ju = { reviews,  0,    bu, nullptr,
                     PREK(9),  bl1 + 1*CC, yu,
                     PREK(0),  tU, NU };
        P0Job js = { overview, 6144, bs, xs,
                     PREK(32), blS1, ys,
                     PREK(1),  tS, NS };
        p0_mega<<<P0_TOT, 256>>>(ju, js, e_u2s, e_g2s, e_w2s, e_t2s, off, cur, csr);
    }

    // ---- gather 1 + s->g/w/t scatter (fused) ----
    {
        ScatJob s0 = { xs, e_g2s + E_GS, e_g2s, agg + AGG_G };
        ScatJob s1 = { xs, e_w2s + E_WS, e_w2s, agg + AGG_W };
        ScatJob s2 = { xs, e_t2s + E_TS, e_t2s, agg + AGG_T };
        gather_scatter<<<GATH_BLK + SCAT_BLK, 256>>>(tU, tS, tG, tW, tT, ys, yu,
                                                     off, csr, s0, s1, s2);
    }

    // ---- wave2 ----
    {
        DualJobP d0 = { yu, PREK(16), tU2, PREK(25), bl2 + 1*CC, xu2, NU, 1 };
        DualJobP d1 = { ys, PREK(17), tS2, PREK(33), blS2,       xs2, NS, 1 };
        FBJobP f0 = { agg + AGG_W, PREK(5), xwp, cnt + CNT_W, PREK(20), tW2, NW };
        FBJobP f1 = { agg + AGG_G, PREK(3), xgp, cnt + CNT_G, PREK(18), tG2, NG };
        FBJobP f2 = { agg + AGG_T, PREK(7), xtp, cnt + CNT_T, PREK(22), tT2, NT };
        wave2<<<W2_TOT, 256>>>(d0, d1, f0, f1, f2);
    }

    // ---- gather 2 ----
    {
        ScatJob sd = { nullptr, nullptr, nullptr, nullptr };
        gather_scatter<<<GATH_BLK, 256>>>(tU2, tS2, tG2, tW2, tT2, xs2, xu2,
                                          off, csr, sd, sd, sd);
    }

    // ---- classifier ----
    dot_score<<<E_LI*16/256, 256>>>(xu2, xs2, eli, eli + E_LI, out, E_LI);
}